// round 1
// baseline (speedup 1.0000x reference)
#include <cuda_runtime.h>
#include <math.h>

#define Bc   2
#define Nc   256
#define INc  256
#define Hc   8
#define Dc   64
#define HDc  512
#define ALPHA 0.2f
#define LN_EPS 1e-5f

// ---- scratch (device globals: allocation-free rule) ----
__device__ float g_xn[Bc * Nc * INc];            // masked nodes
__device__ float g_hs[Bc * Nc * HDc];            // xn @ Ws
__device__ float g_ht[Bc * Nc * HDc];            // xn @ Wt
__device__ float g_scores[(size_t)Bc * Nc * Nc * Hc];   // raw scores (16 MB)
__device__ float g_z3[(size_t)Bc * Nc * Nc * INc];      // xe @ Wedge3 (128 MB)
__device__ float g_z1[Bc * Nc * INc];            // nn_proj @ Wedge1 (per i)
__device__ float g_z2[Bc * Nc * INc];            // nn_proj @ Wedge2 (per j)

// ============================================================
// K1: xn = emb_node * mask ; h_s = xn@Ws ; h_t = xn@Wt
// grid = B*N blocks, 512 threads (one thread per output column)
// ============================================================
__global__ void k1_nodes(const float* __restrict__ emb_node,
                         const float* __restrict__ mask,
                         const float* __restrict__ Ws,
                         const float* __restrict__ Wt) {
    int bi = blockIdx.x;                  // b*N + i
    __shared__ float xsh[INc];
    int t = threadIdx.x;
    float m = mask[bi];
    if (t < INc) {
        float v = emb_node[(size_t)bi * INc + t] * m;
        xsh[t] = v;
        g_xn[(size_t)bi * INc + t] = v;
    }
    __syncthreads();
    float s = 0.f, tt = 0.f;
    #pragma unroll 8
    for (int k = 0; k < INc; k++) {
        float x = xsh[k];
        s  += x * Ws[(size_t)k * HDc + t];
        tt += x * Wt[(size_t)k * HDc + t];
    }
    g_hs[(size_t)bi * HDc + t] = s;
    g_ht[(size_t)bi * HDc + t] = tt;
}

// ============================================================
// K2: the big fused kernel.
// Per block: one (b,i), tile of 32 j's.
//   phase1: h_e tile (32x512) in registers, K=256 from SMEM
//   epilogue: logits -> exp -> raw scores (no h_e store)
//   phase2: z3 tile (32x256) = xe @ Wedge[512:768]
// 256 threads: warp w owns rows 4w..4w+3, lane l owns cols {l+32c}
// Static SMEM exactly 48KB: xe tile (32x256) + B tile (8x512)
// ============================================================
__global__ void __launch_bounds__(256, 2)
k2_big(const float* __restrict__ emb_edge,
       const float* __restrict__ adj,
       const float* __restrict__ mask,
       const float* __restrict__ We,
       const float* __restrict__ Wedge,
       const float* __restrict__ attn) {
    __shared__ float xe_sh[32 * INc];     // 32 KB, persists whole block
    __shared__ float b_sh[8 * HDc];       // 16 KB, staged per K-chunk

    int bid = blockIdx.x;
    int jt = bid & 7;
    int i  = (bid >> 3) & 255;
    int b  = bid >> 11;
    int j0 = jt * 32;
    int t = threadIdx.x;
    int w = t >> 5;
    int l = t & 31;

    float mi = mask[b * Nc + i];

    // load xe tile (masked), 32 rows x 256 cols, float4
    {
        const float4* e4 = (const float4*)(emb_edge +
            ((size_t)(b * Nc + i) * Nc + j0) * INc);
        float4* xs4 = (float4*)xe_sh;
        for (int u = t; u < 32 * 64; u += 256) {
            int r = u >> 6, c = u & 63;
            float4 v = e4[(size_t)r * 64 + c];
            float mm = mi * mask[b * Nc + j0 + r];
            v.x *= mm; v.y *= mm; v.z *= mm; v.w *= mm;
            xs4[r * 64 + c] = v;
        }
    }
    __syncthreads();

    // ---------- phase 1: h_e = xe @ We (32 x 512) ----------
    float acc[4][16];
    #pragma unroll
    for (int r = 0; r < 4; r++)
        #pragma unroll
        for (int c = 0; c < 16; c++) acc[r][c] = 0.f;

    for (int k0 = 0; k0 < INc; k0 += 8) {
        const float4* w4 = (const float4*)(We + (size_t)k0 * HDc);
        float4* b4 = (float4*)b_sh;
        #pragma unroll
        for (int u = t; u < 8 * 128; u += 256) b4[u] = w4[u];
        __syncthreads();
        #pragma unroll
        for (int kk = 0; kk < 8; kk++) {
            float a0 = xe_sh[(4 * w + 0) * INc + k0 + kk];
            float a1 = xe_sh[(4 * w + 1) * INc + k0 + kk];
            float a2 = xe_sh[(4 * w + 2) * INc + k0 + kk];
            float a3 = xe_sh[(4 * w + 3) * INc + k0 + kk];
            #pragma unroll
            for (int c = 0; c < 16; c++) {
                float bv = b_sh[kk * HDc + l + 32 * c];
                acc[0][c] = fmaf(a0, bv, acc[0][c]);
                acc[1][c] = fmaf(a1, bv, acc[1][c]);
                acc[2][c] = fmaf(a2, bv, acc[2][c]);
                acc[3][c] = fmaf(a3, bv, acc[3][c]);
            }
        }
        __syncthreads();
    }

    // ---------- epilogue: logits -> raw scores ----------
    const float* hsrow = g_hs + (size_t)(b * Nc + i) * HDc;
    #pragma unroll 1
    for (int r = 0; r < 4; r++) {
        int j = j0 + 4 * w + r;
        const float* htrow = g_ht + (size_t)(b * Nc + j) * HDc;
        float ah[8];
        #pragma unroll
        for (int h = 0; h < 8; h++) ah[h] = 0.f;
        #pragma unroll
        for (int c = 0; c < 16; c++) {
            int col = 32 * c + l;
            float v = hsrow[col] + htrow[col] + acc[r][c];
            v = (v > 0.f) ? v : ALPHA * v;
            ah[c >> 1] = fmaf(attn[col], v, ah[c >> 1]);   // head = c/2
        }
        #pragma unroll
        for (int off = 16; off > 0; off >>= 1)
            #pragma unroll
            for (int h = 0; h < 8; h++)
                ah[h] += __shfl_xor_sync(0xffffffffu, ah[h], off);
        if (l < 8) {
            size_t eidx = ((size_t)(b * Nc + i) * Nc + j);
            float em = mi * mask[b * Nc + j];
            g_scores[eidx * Hc + l] = expf(ah[l]) * adj[eidx] * em;
        }
    }

    // ---------- phase 2: z3 = xe @ Wedge[512:768] (32 x 256) ----------
    float ac2[4][8];
    #pragma unroll
    for (int r = 0; r < 4; r++)
        #pragma unroll
        for (int c = 0; c < 8; c++) ac2[r][c] = 0.f;

    const float* W3 = Wedge + (size_t)512 * INc;
    for (int k0 = 0; k0 < INc; k0 += 8) {
        const float4* w4 = (const float4*)(W3 + (size_t)k0 * INc);
        float4* b4 = (float4*)b_sh;
        #pragma unroll
        for (int u = t; u < 8 * 64; u += 256) b4[u] = w4[u];
        __syncthreads();
        #pragma unroll
        for (int kk = 0; kk < 8; kk++) {
            float a0 = xe_sh[(4 * w + 0) * INc + k0 + kk];
            float a1 = xe_sh[(4 * w + 1) * INc + k0 + kk];
            float a2 = xe_sh[(4 * w + 2) * INc + k0 + kk];
            float a3 = xe_sh[(4 * w + 3) * INc + k0 + kk];
            #pragma unroll
            for (int c = 0; c < 8; c++) {
                float bv = b_sh[kk * INc + l + 32 * c];
                ac2[0][c] = fmaf(a0, bv, ac2[0][c]);
                ac2[1][c] = fmaf(a1, bv, ac2[1][c]);
                ac2[2][c] = fmaf(a2, bv, ac2[2][c]);
                ac2[3][c] = fmaf(a3, bv, ac2[3][c]);
            }
        }
        __syncthreads();
    }
    #pragma unroll
    for (int r = 0; r < 4; r++) {
        size_t e = ((size_t)(b * Nc + i) * Nc + j0 + 4 * w + r);
        #pragma unroll
        for (int c = 0; c < 8; c++)
            g_z3[e * INc + 32 * c + l] = ac2[r][c];
    }
}

// ============================================================
// K3: per (b,i): softmax denom, new_node einsum, @Wn+bn,
//     z1/z2 projections, out_node LayerNorm.
// grid = B*N blocks, 256 threads.
// ============================================================
__global__ void k3_node(const float* __restrict__ Wn,
                        const float* __restrict__ bn,
                        const float* __restrict__ Wedge,
                        const float* __restrict__ gamma_x,
                        const float* __restrict__ beta_x,
                        float* __restrict__ out_node) {
    int bi = blockIdx.x;
    int b = bi / Nc;
    __shared__ float s_sh[Nc * Hc];     // 8 KB (normalized scores)
    __shared__ float inv[Hc];
    __shared__ float nn_part[4][Dc];
    __shared__ float nn_sh[Dc];
    __shared__ float np_sh[INc];
    __shared__ float red[256];
    int t = threadIdx.x;

    const float* srow = g_scores + (size_t)bi * Nc * Hc;
    #pragma unroll
    for (int u = 0; u < 8; u++) s_sh[t * 8 + u] = srow[t * 8 + u];
    __syncthreads();
    if (t < Hc) {
        float sm = 0.f;
        for (int j = 0; j < Nc; j++) sm += s_sh[j * 8 + t];
        inv[t] = 1.f / (sm + 1e-6f);
    }
    __syncthreads();
    #pragma unroll
    for (int u = 0; u < 8; u++) s_sh[t * 8 + u] *= inv[u];
    __syncthreads();

    // new_node[d] = sum_{j,h} snorm[j,h] * h_t[b,j,h,d]
    int d = t & 63, ch = t >> 6;
    float accn = 0.f;
    const float* htb = g_ht + (size_t)b * Nc * HDc;
    for (int j = ch * 64; j < ch * 64 + 64; j++) {
        const float* htr = htb + (size_t)j * HDc + d;
        #pragma unroll
        for (int h = 0; h < 8; h++)
            accn = fmaf(s_sh[j * 8 + h], htr[h * 64], accn);
    }
    nn_part[ch][d] = accn;
    __syncthreads();
    if (t < Dc)
        nn_sh[t] = nn_part[0][t] + nn_part[1][t] + nn_part[2][t] + nn_part[3][t];
    __syncthreads();

    // nn_proj = new_node @ Wn + bn
    float p = bn[t];
    #pragma unroll 8
    for (int dd = 0; dd < Dc; dd++)
        p = fmaf(nn_sh[dd], Wn[(size_t)dd * INc + t], p);
    np_sh[t] = p;
    __syncthreads();

    // z1 = nn_proj @ Wedge[0:256], z2 = nn_proj @ Wedge[256:512]
    float z1v = 0.f, z2v = 0.f;
    #pragma unroll 4
    for (int k = 0; k < INc; k++) {
        float np = np_sh[k];
        z1v = fmaf(np, Wedge[(size_t)k * INc + t], z1v);
        z2v = fmaf(np, Wedge[(size_t)(k + 256) * INc + t], z2v);
    }
    g_z1[(size_t)bi * INc + t] = z1v;
    g_z2[(size_t)bi * INc + t] = z2v;

    // out_node = LN(xn + nn_proj)
    float v = g_xn[(size_t)bi * INc + t] + p;
    red[t] = v; __syncthreads();
    for (int s = 128; s > 0; s >>= 1) { if (t < s) red[t] += red[t + s]; __syncthreads(); }
    float mean = red[0] * (1.f / 256.f);
    __syncthreads();
    float dv = v - mean;
    red[t] = dv * dv; __syncthreads();
    for (int s = 128; s > 0; s >>= 1) { if (t < s) red[t] += red[t + s]; __syncthreads(); }
    float var = red[0] * (1.f / 256.f);
    out_node[(size_t)bi * INc + t] =
        dv * rsqrtf(var + LN_EPS) * gamma_x[t] + beta_x[t];
}

// ============================================================
// K4: out_edge = LN(xe + z1_i + z2_j + z3 + bedge)
// one warp per edge row, 8 rows per block.
// ============================================================
__global__ void k4_edge(const float* __restrict__ emb_edge,
                        const float* __restrict__ mask,
                        const float* __restrict__ bedge,
                        const float* __restrict__ gamma_e,
                        const float* __restrict__ beta_e,
                        float* __restrict__ out_edge) {
    int row = blockIdx.x * 8 + (threadIdx.x >> 5);
    int l = threadIdx.x & 31;
    int j = row & 255;
    int i = (row >> 8) & 255;
    int b = row >> 16;
    float em = mask[b * Nc + i] * mask[b * Nc + j];

    const float* e  = emb_edge + (size_t)row * INc;
    const float* z3 = g_z3 + (size_t)row * INc;
    const float* z1 = g_z1 + (size_t)(b * Nc + i) * INc;
    const float* z2 = g_z2 + (size_t)(b * Nc + j) * INc;

    float v[8];
    float sm = 0.f;
    #pragma unroll
    for (int c = 0; c < 8; c++) {
        int col = l + 32 * c;
        float val = e[col] * em + z1[col] + z2[col] + z3[col] + bedge[col];
        v[c] = val;
        sm += val;
    }
    #pragma unroll
    for (int off = 16; off > 0; off >>= 1)
        sm += __shfl_xor_sync(0xffffffffu, sm, off);
    float mean = sm * (1.f / 256.f);
    float vs = 0.f;
    #pragma unroll
    for (int c = 0; c < 8; c++) { float d = v[c] - mean; vs += d * d; }
    #pragma unroll
    for (int off = 16; off > 0; off >>= 1)
        vs += __shfl_xor_sync(0xffffffffu, vs, off);
    float rstd = rsqrtf(vs * (1.f / 256.f) + LN_EPS);
    #pragma unroll
    for (int c = 0; c < 8; c++) {
        int col = l + 32 * c;
        out_edge[(size_t)row * INc + col] =
            (v[c] - mean) * rstd * gamma_e[col] + beta_e[col];
    }
}

// ============================================================
extern "C" void kernel_launch(void* const* d_in, const int* in_sizes, int n_in,
                              void* d_out, int out_size) {
    const float* emb_node = (const float*)d_in[0];
    const float* emb_edge = (const float*)d_in[1];
    const float* adj      = (const float*)d_in[2];
    const float* mask     = (const float*)d_in[3];
    const float* Ws       = (const float*)d_in[4];
    const float* Wt       = (const float*)d_in[5];
    const float* We       = (const float*)d_in[6];
    const float* attn     = (const float*)d_in[7];
    const float* Wn       = (const float*)d_in[8];
    const float* bn       = (const float*)d_in[9];
    const float* Wedge    = (const float*)d_in[10];
    const float* bedge    = (const float*)d_in[11];
    const float* gamma_x  = (const float*)d_in[12];
    const float* beta_x   = (const float*)d_in[13];
    const float* gamma_e  = (const float*)d_in[14];
    const float* beta_e   = (const float*)d_in[15];

    float* out_node = (float*)d_out;
    float* out_edge = out_node + Bc * Nc * INc;

    k1_nodes<<<Bc * Nc, 512>>>(emb_node, mask, Ws, Wt);
    k2_big<<<Bc * Nc * (Nc / 32), 256>>>(emb_edge, adj, mask, We, Wedge, attn);
    k3_node<<<Bc * Nc, 256>>>(Wn, bn, Wedge, gamma_x, beta_x, out_node);
    k4_edge<<<Bc * Nc * Nc / 8, 256>>>(emb_edge, mask, bedge, gamma_e, beta_e, out_edge);
}

// round 2
// speedup vs baseline: 3.1064x; 3.1064x over previous
#include <cuda_runtime.h>
#include <math.h>
#include <stdint.h>

#define Bc   2
#define Nc   256
#define INc  256
#define Hc   8
#define Dc   64
#define HDc  512
#define ALPHA 0.2f
#define LN_EPS 1e-5f

// ---- scratch (device globals: allocation-free rule) ----
__device__ float g_xn[Bc * Nc * INc];
__device__ float g_hs[Bc * Nc * HDc];
__device__ float g_ht[Bc * Nc * HDc];
__device__ float g_scores[(size_t)Bc * Nc * Nc * Hc];
__device__ float g_z1[Bc * Nc * INc];
__device__ float g_z2[Bc * Nc * INc];

// ---- tf32 helpers ----
__device__ __forceinline__ uint32_t f2tf(float x) {
    uint32_t r; asm("cvt.rna.tf32.f32 %0, %1;" : "=r"(r) : "f"(x)); return r;
}
__device__ __forceinline__ void mma8(float* c, uint32_t a0, uint32_t a1,
                                     uint32_t a2, uint32_t a3,
                                     uint32_t b0, uint32_t b1) {
    asm volatile(
        "mma.sync.aligned.m16n8k8.row.col.f32.tf32.tf32.f32 "
        "{%0,%1,%2,%3},{%4,%5,%6,%7},{%8,%9},{%0,%1,%2,%3};\n"
        : "+f"(c[0]), "+f"(c[1]), "+f"(c[2]), "+f"(c[3])
        : "r"(a0), "r"(a1), "r"(a2), "r"(a3), "r"(b0), "r"(b1));
}

// ============================================================
// K1: xn = emb_node*mask; h_{s,t} = xn @ W{s,t}
// grid (64, 2): 8 nodes per block, y selects Ws/Wt. 512 threads.
// ============================================================
__global__ void k1_nodes(const float* __restrict__ emb_node,
                         const float* __restrict__ mask,
                         const float* __restrict__ Ws,
                         const float* __restrict__ Wt) {
    __shared__ float xs[8][INc];
    int t = threadIdx.x;
    int n0 = blockIdx.x * 8;
    const float* W  = blockIdx.y ? Wt : Ws;
    float* out      = blockIdx.y ? g_ht : g_hs;
    for (int u = t; u < 8 * INc; u += 512) {
        int r = u >> 8, c = u & 255;
        float v = emb_node[(size_t)(n0 + r) * INc + c] * mask[n0 + r];
        xs[r][c] = v;
        if (blockIdx.y == 0) g_xn[(size_t)(n0 + r) * INc + c] = v;
    }
    __syncthreads();
    float a[8];
    #pragma unroll
    for (int r = 0; r < 8; r++) a[r] = 0.f;
    #pragma unroll 4
    for (int k = 0; k < INc; k++) {
        float wv = W[(size_t)k * HDc + t];
        #pragma unroll
        for (int r = 0; r < 8; r++) a[r] = fmaf(xs[r][k], wv, a[r]);
    }
    #pragma unroll
    for (int r = 0; r < 8; r++)
        out[(size_t)(n0 + r) * HDc + t] = a[r];
}

// ============================================================
// K2: tf32 tensor-core scores kernel.
// Block = (b, i, 64-j tile). C tile 64x512, K=256. 8 warps,
// warp tile 64x64 (warp w == head w). Epilogue: lrelu+attn-dot
// +exp with ht staged per 16-row quarter (reusing B buffers).
// SMEM (floats): A[64][260] | B 2x[8][520] (reuse: ht[16][516]) | hs[512] | at[512]
// ============================================================
#define K2_SMEM_F (16640 + 8320 + 512 + 512)
__global__ void __launch_bounds__(256, 1)
k2_scores(const float* __restrict__ emb_edge,
          const float* __restrict__ adj,
          const float* __restrict__ mask,
          const float* __restrict__ We,
          const float* __restrict__ attn) {
    extern __shared__ float sm[];
    uint32_t* sA  = (uint32_t*)sm;            // tf32, pitch 260
    uint32_t* sB  = (uint32_t*)(sm + 16640);  // tf32, 2 bufs pitch 520
    float*    sHT = sm + 16640;               // fp32 reuse, pitch 516
    float*    sHS = sm + 24960;
    float*    sAT = sm + 25472;

    int t = threadIdx.x, w = t >> 5, lane = t & 31;
    int g = lane >> 2, tig = lane & 3;
    int bid = blockIdx.x;
    int jt = bid & 3, i = (bid >> 2) & 255, b = bid >> 10;
    int j0 = jt * 64, bi = b * Nc + i;
    float mi = mask[bi];

    // stage A (masked xe -> tf32)
    #pragma unroll
    for (int u = 0; u < 16; u++) {
        int lin = u * 256 + t;
        int r = lin >> 6, c4 = lin & 63;
        float4 v = *(const float4*)(emb_edge +
            (((size_t)bi * Nc) + j0 + r) * INc + c4 * 4);
        float mm = mi * mask[b * Nc + j0 + r];
        uint4 dv;
        dv.x = f2tf(v.x * mm); dv.y = f2tf(v.y * mm);
        dv.z = f2tf(v.z * mm); dv.w = f2tf(v.w * mm);
        *(uint4*)(sA + r * 260 + c4 * 4) = dv;
    }
    {
        const float* hsrow = g_hs + (size_t)bi * HDc;
        for (int u = t; u < 512; u += 256) { sHS[u] = hsrow[u]; sAT[u] = attn[u]; }
    }

    float acc[4][8][4];
    #pragma unroll
    for (int m = 0; m < 4; m++)
        #pragma unroll
        for (int n = 0; n < 8; n++)
            #pragma unroll
            for (int e = 0; e < 4; e++) acc[m][n][e] = 0.f;

    float4 breg[4];
    #pragma unroll
    for (int u = 0; u < 4; u++) {
        int lin = u * 256 + t; int kr = lin >> 7, c4 = lin & 127;
        breg[u] = *(const float4*)(We + (size_t)kr * HDc + c4 * 4);
    }
    #pragma unroll
    for (int u = 0; u < 4; u++) {
        int lin = u * 256 + t; int kr = lin >> 7, c4 = lin & 127;
        uint4 dv; dv.x = f2tf(breg[u].x); dv.y = f2tf(breg[u].y);
        dv.z = f2tf(breg[u].z); dv.w = f2tf(breg[u].w);
        *(uint4*)(sB + kr * 520 + c4 * 4) = dv;
    }

    for (int c = 0; c < 32; c++) {
        __syncthreads();
        if (c + 1 < 32) {
            #pragma unroll
            for (int u = 0; u < 4; u++) {
                int lin = u * 256 + t; int kr = lin >> 7, c4 = lin & 127;
                breg[u] = *(const float4*)(We +
                    (size_t)((c + 1) * 8 + kr) * HDc + c4 * 4);
            }
        }
        const uint32_t* Bb = sB + (c & 1) * 4160;
        int kc = c * 8;
        uint32_t af[4][4];
        #pragma unroll
        for (int m = 0; m < 4; m++) {
            const uint32_t* Ar = sA + (m * 16 + g) * 260 + kc + tig;
            af[m][0] = Ar[0];        af[m][2] = Ar[4];
            af[m][1] = Ar[8 * 260];  af[m][3] = Ar[8 * 260 + 4];
        }
        #pragma unroll
        for (int n = 0; n < 8; n++) {
            int col = w * 64 + n * 8 + g;
            uint32_t b0 = Bb[tig * 520 + col];
            uint32_t b1 = Bb[(tig + 4) * 520 + col];
            #pragma unroll
            for (int m = 0; m < 4; m++)
                mma8(acc[m][n], af[m][0], af[m][1], af[m][2], af[m][3], b0, b1);
        }
        if (c + 1 < 32) {
            uint32_t* d0 = sB + ((c + 1) & 1) * 4160;
            #pragma unroll
            for (int u = 0; u < 4; u++) {
                int lin = u * 256 + t; int kr = lin >> 7, c4 = lin & 127;
                uint4 dv; dv.x = f2tf(breg[u].x); dv.y = f2tf(breg[u].y);
                dv.z = f2tf(breg[u].z); dv.w = f2tf(breg[u].w);
                *(uint4*)(d0 + kr * 520 + c4 * 4) = dv;
            }
        }
    }

    // ---- epilogue ----
    float hsr[16], atr[16];
    #pragma unroll
    for (int n = 0; n < 8; n++) {
        float2 h2 = *(const float2*)(sHS + w * 64 + n * 8 + 2 * tig);
        float2 a2 = *(const float2*)(sAT + w * 64 + n * 8 + 2 * tig);
        hsr[2 * n] = h2.x; hsr[2 * n + 1] = h2.y;
        atr[2 * n] = a2.x; atr[2 * n + 1] = a2.y;
    }
    #pragma unroll
    for (int q = 0; q < 4; q++) {
        __syncthreads();
        #pragma unroll
        for (int u = 0; u < 8; u++) {
            int lin = u * 256 + t;
            int r = lin >> 7, c4 = lin & 127;
            float4 v = *(const float4*)(g_ht +
                ((size_t)(b * Nc) + j0 + q * 16 + r) * HDc + c4 * 4);
            *(float4*)(sHT + r * 516 + c4 * 4) = v;
        }
        __syncthreads();
        #pragma unroll
        for (int rh = 0; rh < 2; rh++) {
            int lr = g + 8 * rh;
            float sum = 0.f;
            #pragma unroll
            for (int n = 0; n < 8; n++) {
                float2 hte = *(const float2*)(sHT + lr * 516 + w * 64 + n * 8 + 2 * tig);
                float v0 = acc[q][n][2 * rh]     + hsr[2 * n]     + hte.x;
                float v1 = acc[q][n][2 * rh + 1] + hsr[2 * n + 1] + hte.y;
                v0 = v0 > 0.f ? v0 : ALPHA * v0;
                v1 = v1 > 0.f ? v1 : ALPHA * v1;
                sum = fmaf(atr[2 * n], v0, sum);
                sum = fmaf(atr[2 * n + 1], v1, sum);
            }
            sum += __shfl_xor_sync(0xffffffffu, sum, 1);
            sum += __shfl_xor_sync(0xffffffffu, sum, 2);
            if (tig == 0) {
                int j = j0 + q * 16 + lr;
                size_t e = (size_t)bi * Nc + j;
                g_scores[e * 8 + w] = expf(sum) * adj[e] * (mi * mask[b * Nc + j]);
            }
        }
    }
}

// ============================================================
// K3: per (b,i): softmax denom, new_node einsum, @Wn+bn,
//     z1/z2 projections, out_node LayerNorm. (unchanged)
// ============================================================
__global__ void k3_node(const float* __restrict__ Wn,
                        const float* __restrict__ bn,
                        const float* __restrict__ Wedge,
                        const float* __restrict__ gamma_x,
                        const float* __restrict__ beta_x,
                        float* __restrict__ out_node) {
    int bi = blockIdx.x;
    int b = bi / Nc;
    __shared__ float s_sh[Nc * Hc];
    __shared__ float inv[Hc];
    __shared__ float nn_part[4][Dc];
    __shared__ float nn_sh[Dc];
    __shared__ float np_sh[INc];
    __shared__ float red[256];
    int t = threadIdx.x;

    const float* srow = g_scores + (size_t)bi * Nc * Hc;
    #pragma unroll
    for (int u = 0; u < 8; u++) s_sh[t * 8 + u] = srow[t * 8 + u];
    __syncthreads();
    if (t < Hc) {
        float smv = 0.f;
        for (int j = 0; j < Nc; j++) smv += s_sh[j * 8 + t];
        inv[t] = 1.f / (smv + 1e-6f);
    }
    __syncthreads();
    #pragma unroll
    for (int u = 0; u < 8; u++) s_sh[t * 8 + u] *= inv[u];
    __syncthreads();

    int d = t & 63, ch = t >> 6;
    float accn = 0.f;
    const float* htb = g_ht + (size_t)b * Nc * HDc;
    for (int j = ch * 64; j < ch * 64 + 64; j++) {
        const float* htr = htb + (size_t)j * HDc + d;
        #pragma unroll
        for (int h = 0; h < 8; h++)
            accn = fmaf(s_sh[j * 8 + h], htr[h * 64], accn);
    }
    nn_part[ch][d] = accn;
    __syncthreads();
    if (t < Dc)
        nn_sh[t] = nn_part[0][t] + nn_part[1][t] + nn_part[2][t] + nn_part[3][t];
    __syncthreads();

    float p = bn[t];
    #pragma unroll 8
    for (int dd = 0; dd < Dc; dd++)
        p = fmaf(nn_sh[dd], Wn[(size_t)dd * INc + t], p);
    np_sh[t] = p;
    __syncthreads();

    float z1v = 0.f, z2v = 0.f;
    #pragma unroll 4
    for (int k = 0; k < INc; k++) {
        float np = np_sh[k];
        z1v = fmaf(np, Wedge[(size_t)k * INc + t], z1v);
        z2v = fmaf(np, Wedge[(size_t)(k + 256) * INc + t], z2v);
    }
    g_z1[(size_t)bi * INc + t] = z1v;
    g_z2[(size_t)bi * INc + t] = z2v;

    float v = g_xn[(size_t)bi * INc + t] + p;
    red[t] = v; __syncthreads();
    for (int s = 128; s > 0; s >>= 1) { if (t < s) red[t] += red[t + s]; __syncthreads(); }
    float mean = red[0] * (1.f / 256.f);
    __syncthreads();
    float dv = v - mean;
    red[t] = dv * dv; __syncthreads();
    for (int s = 128; s > 0; s >>= 1) { if (t < s) red[t] += red[t + s]; __syncthreads(); }
    float var = red[0] * (1.f / 256.f);
    out_node[(size_t)bi * INc + t] =
        dv * rsqrtf(var + LN_EPS) * gamma_x[t] + beta_x[t];
}

// ============================================================
// K4: fused z3 GEMM (xe @ W3, tf32) + edge residual + LayerNorm.
// Block = (b, i, 64-j tile). C tile 64x256. Warp tile 64x32.
// SMEM (floats): A[64][260] fp32 | B 2x[8][264] (reuse z2[16][260])
//                | z1,be,ga,bt 256 each | red 2x128 | mean/rstd 16
// ============================================================
#define K4_SMEM_F (16640 + 4224 + 4 * 256 + 256 + 32)
__global__ void __launch_bounds__(256, 1)
k4_fused(const float* __restrict__ emb_edge,
         const float* __restrict__ mask,
         const float* __restrict__ Wedge,
         const float* __restrict__ bedge,
         const float* __restrict__ gamma_e,
         const float* __restrict__ beta_e,
         float* __restrict__ out_edge) {
    extern __shared__ float sm[];
    float*    sA   = sm;                      // fp32 masked xe, pitch 260
    uint32_t* sB   = (uint32_t*)(sm + 16640); // tf32, 2 bufs pitch 264
    float*    sZ2  = sm + 16640;              // reuse, pitch 260
    float*    sZ1  = sm + 20864;
    float*    sBE  = sm + 21120;
    float*    sGA  = sm + 21376;
    float*    sBT  = sm + 21632;
    float*    sRed = sm + 21888;
    float*    sRedQ= sm + 22016;
    float*    sMean= sm + 22144;
    float*    sRstd= sm + 22160;

    int t = threadIdx.x, w = t >> 5, lane = t & 31;
    int g = lane >> 2, tig = lane & 3;
    int bid = blockIdx.x;
    int jt = bid & 3, i = (bid >> 2) & 255, b = bid >> 10;
    int j0 = jt * 64, bi = b * Nc + i;
    float mi = mask[bi];

    #pragma unroll
    for (int u = 0; u < 16; u++) {
        int lin = u * 256 + t;
        int r = lin >> 6, c4 = lin & 63;
        float4 v = *(const float4*)(emb_edge +
            (((size_t)bi * Nc) + j0 + r) * INc + c4 * 4);
        float mm = mi * mask[b * Nc + j0 + r];
        v.x *= mm; v.y *= mm; v.z *= mm; v.w *= mm;
        *(float4*)(sA + r * 260 + c4 * 4) = v;
    }
    sZ1[t] = g_z1[(size_t)bi * INc + t];
    sBE[t] = bedge[t]; sGA[t] = gamma_e[t]; sBT[t] = beta_e[t];

    float acc[4][4][4];
    #pragma unroll
    for (int m = 0; m < 4; m++)
        #pragma unroll
        for (int n = 0; n < 4; n++)
            #pragma unroll
            for (int e = 0; e < 4; e++) acc[m][n][e] = 0.f;

    const float* W3 = Wedge + (size_t)512 * INc;
    float4 breg[2];
    #pragma unroll
    for (int u = 0; u < 2; u++) {
        int lin = u * 256 + t; int kr = lin >> 6, c4 = lin & 63;
        breg[u] = *(const float4*)(W3 + (size_t)kr * INc + c4 * 4);
    }
    #pragma unroll
    for (int u = 0; u < 2; u++) {
        int lin = u * 256 + t; int kr = lin >> 6, c4 = lin & 63;
        uint4 dv; dv.x = f2tf(breg[u].x); dv.y = f2tf(breg[u].y);
        dv.z = f2tf(breg[u].z); dv.w = f2tf(breg[u].w);
        *(uint4*)(sB + kr * 264 + c4 * 4) = dv;
    }

    for (int c = 0; c < 32; c++) {
        __syncthreads();
        if (c + 1 < 32) {
            #pragma unroll
            for (int u = 0; u < 2; u++) {
                int lin = u * 256 + t; int kr = lin >> 6, c4 = lin & 63;
                breg[u] = *(const float4*)(W3 +
                    (size_t)((c + 1) * 8 + kr) * INc + c4 * 4);
            }
        }
        const uint32_t* Bb = sB + (c & 1) * 2112;
        int kc = c * 8;
        uint32_t af[4][4];
        #pragma unroll
        for (int m = 0; m < 4; m++) {
            const float* Ar = sA + (m * 16 + g) * 260 + kc + tig;
            af[m][0] = f2tf(Ar[0]);        af[m][2] = f2tf(Ar[4]);
            af[m][1] = f2tf(Ar[8 * 260]);  af[m][3] = f2tf(Ar[8 * 260 + 4]);
        }
        #pragma unroll
        for (int n = 0; n < 4; n++) {
            int col = w * 32 + n * 8 + g;
            uint32_t b0 = Bb[tig * 264 + col];
            uint32_t b1 = Bb[(tig + 4) * 264 + col];
            #pragma unroll
            for (int m = 0; m < 4; m++)
                mma8(acc[m][n], af[m][0], af[m][1], af[m][2], af[m][3], b0, b1);
        }
        if (c + 1 < 32) {
            uint32_t* d0 = sB + ((c + 1) & 1) * 2112;
            #pragma unroll
            for (int u = 0; u < 2; u++) {
                int lin = u * 256 + t; int kr = lin >> 6, c4 = lin & 63;
                uint4 dv; dv.x = f2tf(breg[u].x); dv.y = f2tf(breg[u].y);
                dv.z = f2tf(breg[u].z); dv.w = f2tf(breg[u].w);
                *(uint4*)(d0 + kr * 264 + c4 * 4) = dv;
            }
        }
    }

    // ---- epilogue: residual + LayerNorm ----
    float z1r[8], ber[8], gar[8], btr[8];
    #pragma unroll
    for (int n = 0; n < 4; n++) {
        int c0 = w * 32 + n * 8 + 2 * tig;
        float2 a = *(const float2*)(sZ1 + c0);
        float2 bb = *(const float2*)(sBE + c0);
        float2 gg = *(const float2*)(sGA + c0);
        float2 tt = *(const float2*)(sBT + c0);
        z1r[2 * n] = a.x;  z1r[2 * n + 1] = a.y;
        ber[2 * n] = bb.x; ber[2 * n + 1] = bb.y;
        gar[2 * n] = gg.x; gar[2 * n + 1] = gg.y;
        btr[2 * n] = tt.x; btr[2 * n + 1] = tt.y;
    }
    #pragma unroll
    for (int q = 0; q < 4; q++) {
        __syncthreads();
        #pragma unroll
        for (int u = 0; u < 4; u++) {
            int lin = u * 256 + t;
            int r = lin >> 6, c4 = lin & 63;
            float4 v = *(const float4*)(g_z2 +
                ((size_t)(b * Nc) + j0 + q * 16 + r) * INc + c4 * 4);
            *(float4*)(sZ2 + r * 260 + c4 * 4) = v;
        }
        __syncthreads();
        float vv[2][8];
        #pragma unroll
        for (int rh = 0; rh < 2; rh++) {
            int lr = g + 8 * rh;
            float sum = 0.f, sq = 0.f;
            #pragma unroll
            for (int n = 0; n < 4; n++) {
                int c0 = w * 32 + n * 8 + 2 * tig;
                float2 xe2 = *(const float2*)(sA + (q * 16 + lr) * 260 + c0);
                float2 z22 = *(const float2*)(sZ2 + lr * 260 + c0);
                float v0 = acc[q][n][2 * rh]     + xe2.x + z1r[2 * n]     + z22.x + ber[2 * n];
                float v1 = acc[q][n][2 * rh + 1] + xe2.y + z1r[2 * n + 1] + z22.y + ber[2 * n + 1];
                vv[rh][2 * n] = v0; vv[rh][2 * n + 1] = v1;
                sum += v0 + v1; sq = fmaf(v0, v0, sq); sq = fmaf(v1, v1, sq);
            }
            sum += __shfl_xor_sync(0xffffffffu, sum, 1);
            sum += __shfl_xor_sync(0xffffffffu, sum, 2);
            sq  += __shfl_xor_sync(0xffffffffu, sq, 1);
            sq  += __shfl_xor_sync(0xffffffffu, sq, 2);
            if (tig == 0) { sRed[lr * 8 + w] = sum; sRedQ[lr * 8 + w] = sq; }
        }
        __syncthreads();
        if (t < 16) {
            float s = 0.f, ss = 0.f;
            #pragma unroll
            for (int k = 0; k < 8; k++) { s += sRed[t * 8 + k]; ss += sRedQ[t * 8 + k]; }
            float mean = s * (1.f / 256.f);
            float var = ss * (1.f / 256.f) - mean * mean;
            sMean[t] = mean; sRstd[t] = rsqrtf(var + LN_EPS);
        }
        __syncthreads();
        #pragma unroll
        for (int rh = 0; rh < 2; rh++) {
            int lr = g + 8 * rh;
            float mean = sMean[lr], rs = sRstd[lr];
            int j = j0 + q * 16 + lr;
            float* orow = out_edge + ((size_t)bi * Nc + j) * INc;
            #pragma unroll
            for (int n = 0; n < 4; n++) {
                int c0 = w * 32 + n * 8 + 2 * tig;
                float2 o;
                o.x = (vv[rh][2 * n]     - mean) * rs * gar[2 * n]     + btr[2 * n];
                o.y = (vv[rh][2 * n + 1] - mean) * rs * gar[2 * n + 1] + btr[2 * n + 1];
                *(float2*)(orow + c0) = o;
            }
        }
    }
}

// ============================================================
extern "C" void kernel_launch(void* const* d_in, const int* in_sizes, int n_in,
                              void* d_out, int out_size) {
    const float* emb_node = (const float*)d_in[0];
    const float* emb_edge = (const float*)d_in[1];
    const float* adj      = (const float*)d_in[2];
    const float* mask     = (const float*)d_in[3];
    const float* Ws       = (const float*)d_in[4];
    const float* Wt       = (const float*)d_in[5];
    const float* We       = (const float*)d_in[6];
    const float* attn     = (const float*)d_in[7];
    const float* Wn       = (const float*)d_in[8];
    const float* bn       = (const float*)d_in[9];
    const float* Wedge    = (const float*)d_in[10];
    const float* bedge    = (const float*)d_in[11];
    const float* gamma_x  = (const float*)d_in[12];
    const float* beta_x   = (const float*)d_in[13];
    const float* gamma_e  = (const float*)d_in[14];
    const float* beta_e   = (const float*)d_in[15];

    float* out_node = (float*)d_out;
    float* out_edge = out_node + Bc * Nc * INc;

    cudaFuncSetAttribute(k2_scores, cudaFuncAttributeMaxDynamicSharedMemorySize,
                         K2_SMEM_F * 4);
    cudaFuncSetAttribute(k4_fused, cudaFuncAttributeMaxDynamicSharedMemorySize,
                         K4_SMEM_F * 4);

    k1_nodes<<<dim3(64, 2), 512>>>(emb_node, mask, Ws, Wt);
    k2_scores<<<Bc * Nc * 4, 256, K2_SMEM_F * 4>>>(emb_edge, adj, mask, We, attn);
    k3_node<<<Bc * Nc, 256>>>(Wn, bn, Wedge, gamma_x, beta_x, out_node);
    k4_fused<<<Bc * Nc * 4, 256, K4_SMEM_F * 4>>>(emb_edge, mask, Wedge, bedge,
                                                  gamma_e, beta_e, out_edge);
}

// round 3
// speedup vs baseline: 3.5033x; 1.1278x over previous
#include <cuda_runtime.h>
#include <math.h>
#include <stdint.h>

#define Bc   2
#define Nc   256
#define INc  256
#define Hc   8
#define Dc   64
#define HDc  512
#define ALPHA 0.2f
#define LN_EPS 1e-5f

// ---- scratch ----
__device__ float g_xn[Bc * Nc * INc];
__device__ float g_hs[Bc * Nc * HDc];
__device__ float g_ht[Bc * Nc * HDc];
__device__ float g_scores[(size_t)Bc * Nc * Nc * Hc];
__device__ float g_z1[Bc * Nc * INc];
__device__ float g_z2[Bc * Nc * INc];
__device__ uint32_t g_Wet[INc * HDc];     // We in tf32
__device__ uint32_t g_W3t[INc * INc];     // Wedge[512:768] in tf32

__device__ __forceinline__ uint32_t f2tf(float x) {
    uint32_t r; asm("cvt.rna.tf32.f32 %0, %1;" : "=r"(r) : "f"(x)); return r;
}
__device__ __forceinline__ void mma8(float* c, uint32_t a0, uint32_t a1,
                                     uint32_t a2, uint32_t a3,
                                     uint32_t b0, uint32_t b1) {
    asm volatile(
        "mma.sync.aligned.m16n8k8.row.col.f32.tf32.tf32.f32 "
        "{%0,%1,%2,%3},{%4,%5,%6,%7},{%8,%9},{%0,%1,%2,%3};\n"
        : "+f"(c[0]), "+f"(c[1]), "+f"(c[2]), "+f"(c[3])
        : "r"(a0), "r"(a1), "r"(a2), "r"(a3), "r"(b0), "r"(b1));
}
__device__ __forceinline__ void cp16(uint32_t dst, const void* src) {
    asm volatile("cp.async.cg.shared.global [%0], [%1], 16;\n" :: "r"(dst), "l"(src));
}
#define CP_COMMIT asm volatile("cp.async.commit_group;\n" ::)
#define CP_WAIT1  asm volatile("cp.async.wait_group 1;\n" ::)

// ============================================================
// K0: pre-convert weights to tf32
// ============================================================
__global__ void k0_wconv(const float* __restrict__ We,
                         const float* __restrict__ Wedge) {
    int i = blockIdx.x * 512 + threadIdx.x;
    if (i < INc * HDc) g_Wet[i] = f2tf(We[i]);
    int j = i - INc * HDc;
    if (j >= 0 && j < INc * INc) g_W3t[j] = f2tf(Wedge[HDc * INc + j]);
}

// ============================================================
// K1: xn = emb_node*mask; h_{s,t} = xn @ W{s,t}
// ============================================================
__global__ void k1_nodes(const float* __restrict__ emb_node,
                         const float* __restrict__ mask,
                         const float* __restrict__ Ws,
                         const float* __restrict__ Wt) {
    __shared__ float xs[8][INc];
    int t = threadIdx.x;
    int n0 = blockIdx.x * 8;
    const float* W  = blockIdx.y ? Wt : Ws;
    float* out      = blockIdx.y ? g_ht : g_hs;
    for (int u = t; u < 8 * INc; u += 512) {
        int r = u >> 8, c = u & 255;
        float v = emb_node[(size_t)(n0 + r) * INc + c] * mask[n0 + r];
        xs[r][c] = v;
        if (blockIdx.y == 0) g_xn[(size_t)(n0 + r) * INc + c] = v;
    }
    __syncthreads();
    float a[8];
    #pragma unroll
    for (int r = 0; r < 8; r++) a[r] = 0.f;
    #pragma unroll 4
    for (int k = 0; k < INc; k++) {
        float wv = W[(size_t)k * HDc + t];
        #pragma unroll
        for (int r = 0; r < 8; r++) a[r] = fmaf(xs[r][k], wv, a[r]);
    }
    #pragma unroll
    for (int r = 0; r < 8; r++)
        out[(size_t)(n0 + r) * HDc + t] = a[r];
}

// ============================================================
// K2: tf32 scores kernel. 512 threads, 16 warps.
// Block = (b,i,64-j tile). C 64x512, K=256.
// Warp (mr = w>>3, wc = w&7): rows mr*32+[0,32), cols wc*64+[0,64).
// B staged by cp.async, 3 stages, 1 sync/iter.
// SMEM u32: A[64][260]=16640 | B 3x[8][520]=12480 | hs 512 | at 512
// ============================================================
#define K2_SMEM_U (16640 + 12480 + 512 + 512)
__global__ void __launch_bounds__(512, 1)
k2_scores(const float* __restrict__ emb_edge,
          const float* __restrict__ adj,
          const float* __restrict__ mask,
          const float* __restrict__ attn) {
    extern __shared__ uint32_t su[];
    uint32_t* sA  = su;
    uint32_t* sB  = su + 16640;
    float*    sHS = (float*)(su + 29120);
    float*    sAT = (float*)(su + 29632);

    int t = threadIdx.x, w = t >> 5, lane = t & 31;
    int g = lane >> 2, tig = lane & 3;
    int mr = w >> 3, wc = w & 7;
    int bid = blockIdx.x;
    int jt = bid & 3, i = (bid >> 2) & 255, b = bid >> 10;
    int j0 = jt * 64, bi = b * Nc + i;
    float mi = mask[bi];

    uint32_t sBsh = (uint32_t)__cvta_generic_to_shared(sB);

    // prefetch B chunks 0,1
    #pragma unroll
    for (int c = 0; c < 2; c++) {
        #pragma unroll
        for (int u = 0; u < 2; u++) {
            int lin = u * 512 + t; int kr = lin >> 7, c4 = lin & 127;
            cp16(sBsh + (c * 4160 + kr * 520 + c4 * 4) * 4,
                 g_Wet + (size_t)(c * 8 + kr) * HDc + c4 * 4);
        }
        CP_COMMIT;
    }

    // stage A (masked xe -> tf32)
    #pragma unroll
    for (int u = 0; u < 8; u++) {
        int lin = u * 512 + t;
        int r = lin >> 6, c4 = lin & 63;
        float4 v = *(const float4*)(emb_edge +
            (((size_t)bi * Nc) + j0 + r) * INc + c4 * 4);
        float mm = mi * mask[b * Nc + j0 + r];
        uint4 dv;
        dv.x = f2tf(v.x * mm); dv.y = f2tf(v.y * mm);
        dv.z = f2tf(v.z * mm); dv.w = f2tf(v.w * mm);
        *(uint4*)(sA + r * 260 + c4 * 4) = dv;
    }
    sHS[t] = g_hs[(size_t)bi * HDc + t];
    sAT[t] = attn[t];

    float acc[2][8][4];
    #pragma unroll
    for (int m = 0; m < 2; m++)
        #pragma unroll
        for (int n = 0; n < 8; n++)
            #pragma unroll
            for (int e = 0; e < 4; e++) acc[m][n][e] = 0.f;

    for (int c = 0; c < 32; c++) {
        CP_WAIT1;
        __syncthreads();
        if (c + 2 < 32) {
            int cc = c + 2;
            #pragma unroll
            for (int u = 0; u < 2; u++) {
                int lin = u * 512 + t; int kr = lin >> 7, c4 = lin & 127;
                cp16(sBsh + ((cc % 3) * 4160 + kr * 520 + c4 * 4) * 4,
                     g_Wet + (size_t)(cc * 8 + kr) * HDc + c4 * 4);
            }
            CP_COMMIT;
        }
        const uint32_t* Bb = sB + (c % 3) * 4160;
        int kc = c * 8;
        uint32_t af[2][4];
        #pragma unroll
        for (int mf = 0; mf < 2; mf++) {
            const uint32_t* Ar = sA + (mr * 32 + mf * 16 + g) * 260 + kc + tig;
            af[mf][0] = Ar[0];        af[mf][2] = Ar[4];
            af[mf][1] = Ar[8 * 260];  af[mf][3] = Ar[8 * 260 + 4];
        }
        #pragma unroll
        for (int n = 0; n < 8; n++) {
            int col = wc * 64 + n * 8 + g;
            uint32_t b0 = Bb[tig * 520 + col];
            uint32_t b1 = Bb[(tig + 4) * 520 + col];
            mma8(acc[0][n], af[0][0], af[0][1], af[0][2], af[0][3], b0, b1);
            mma8(acc[1][n], af[1][0], af[1][1], af[1][2], af[1][3], b0, b1);
        }
    }

    // ---- epilogue: lrelu + attn-dot + exp (ht direct from L2) ----
    #pragma unroll
    for (int mf = 0; mf < 2; mf++) {
        #pragma unroll
        for (int rh = 0; rh < 2; rh++) {
            int j = j0 + mr * 32 + mf * 16 + g + 8 * rh;
            const float* htrow = g_ht + (size_t)(b * Nc + j) * HDc + wc * 64;
            float sum = 0.f;
            #pragma unroll
            for (int n = 0; n < 8; n++) {
                int c0 = n * 8 + 2 * tig;
                float2 hte = *(const float2*)(htrow + c0);
                float2 hs2 = *(const float2*)(sHS + wc * 64 + c0);
                float2 at2 = *(const float2*)(sAT + wc * 64 + c0);
                float v0 = acc[mf][n][2 * rh]     + hs2.x + hte.x;
                float v1 = acc[mf][n][2 * rh + 1] + hs2.y + hte.y;
                v0 = v0 > 0.f ? v0 : ALPHA * v0;
                v1 = v1 > 0.f ? v1 : ALPHA * v1;
                sum = fmaf(at2.x, v0, sum);
                sum = fmaf(at2.y, v1, sum);
            }
            sum += __shfl_xor_sync(0xffffffffu, sum, 1);
            sum += __shfl_xor_sync(0xffffffffu, sum, 2);
            if (tig == 0) {
                size_t e = (size_t)bi * Nc + j;
                g_scores[e * 8 + wc] = expf(sum) * adj[e] * (mi * mask[b * Nc + j]);
            }
        }
    }
}

// ============================================================
// K3: per (b,i): softmax denom, new_node einsum, @Wn+bn,
//     z1/z2 projections, out_node LayerNorm.
// ============================================================
__global__ void k3_node(const float* __restrict__ Wn,
                        const float* __restrict__ bn,
                        const float* __restrict__ Wedge,
                        const float* __restrict__ gamma_x,
                        const float* __restrict__ beta_x,
                        float* __restrict__ out_node) {
    int bi = blockIdx.x;
    int b = bi / Nc;
    __shared__ float s_sh[Nc * Hc];
    __shared__ float inv[Hc];
    __shared__ float nn_part[4][Dc];
    __shared__ float nn_sh[Dc];
    __shared__ float np_sh[INc];
    __shared__ float red[256];
    int t = threadIdx.x;

    const float* srow = g_scores + (size_t)bi * Nc * Hc;
    #pragma unroll
    for (int u = 0; u < 8; u++) s_sh[t * 8 + u] = srow[t * 8 + u];
    __syncthreads();
    if (t < Hc) {
        float smv = 0.f;
        for (int j = 0; j < Nc; j++) smv += s_sh[j * 8 + t];
        inv[t] = 1.f / (smv + 1e-6f);
    }
    __syncthreads();
    #pragma unroll
    for (int u = 0; u < 8; u++) s_sh[t * 8 + u] *= inv[u];
    __syncthreads();

    int d = t & 63, ch = t >> 6;
    float accn = 0.f;
    const float* htb = g_ht + (size_t)b * Nc * HDc;
    for (int j = ch * 64; j < ch * 64 + 64; j++) {
        const float* htr = htb + (size_t)j * HDc + d;
        #pragma unroll
        for (int h = 0; h < 8; h++)
            accn = fmaf(s_sh[j * 8 + h], htr[h * 64], accn);
    }
    nn_part[ch][d] = accn;
    __syncthreads();
    if (t < Dc)
        nn_sh[t] = nn_part[0][t] + nn_part[1][t] + nn_part[2][t] + nn_part[3][t];
    __syncthreads();

    float p = bn[t];
    #pragma unroll 8
    for (int dd = 0; dd < Dc; dd++)
        p = fmaf(nn_sh[dd], Wn[(size_t)dd * INc + t], p);
    np_sh[t] = p;
    __syncthreads();

    float z1v = 0.f, z2v = 0.f;
    #pragma unroll 4
    for (int k = 0; k < INc; k++) {
        float np = np_sh[k];
        z1v = fmaf(np, Wedge[(size_t)k * INc + t], z1v);
        z2v = fmaf(np, Wedge[(size_t)(k + 256) * INc + t], z2v);
    }
    g_z1[(size_t)bi * INc + t] = z1v;
    g_z2[(size_t)bi * INc + t] = z2v;

    float v = g_xn[(size_t)bi * INc + t] + p;
    red[t] = v; __syncthreads();
    for (int s = 128; s > 0; s >>= 1) { if (t < s) red[t] += red[t + s]; __syncthreads(); }
    float mean = red[0] * (1.f / 256.f);
    __syncthreads();
    float dv = v - mean;
    red[t] = dv * dv; __syncthreads();
    for (int s = 128; s > 0; s >>= 1) { if (t < s) red[t] += red[t + s]; __syncthreads(); }
    float var = red[0] * (1.f / 256.f);
    out_node[(size_t)bi * INc + t] =
        dv * rsqrtf(var + LN_EPS) * gamma_x[t] + beta_x[t];
}

// ============================================================
// K4: fused z3 GEMM + residual + LayerNorm. 512 threads.
// Block = (b,i,64-j tile). C 64x256. Warp 32x32 (mr=w>>3, wc=w&7).
// SMEM u32: A tf32[64][260]=16640 | B 3x[8][264]=6336 | z1 256 |
//           be/ga/bt 768 | red 512 | redq 512 | mean 64 | rstd 64
// ============================================================
#define K4_SMEM_U (16640 + 6336 + 256 + 768 + 512 + 512 + 64 + 64)
__global__ void __launch_bounds__(512, 1)
k4_fused(const float* __restrict__ emb_edge,
         const float* __restrict__ mask,
         const float* __restrict__ bedge,
         const float* __restrict__ gamma_e,
         const float* __restrict__ beta_e,
         float* __restrict__ out_edge) {
    extern __shared__ uint32_t su[];
    uint32_t* sA   = su;
    uint32_t* sB   = su + 16640;
    float*    sZ1  = (float*)(su + 22976);
    float*    sBE  = (float*)(su + 23232);
    float*    sGA  = (float*)(su + 23488);
    float*    sBT  = (float*)(su + 23744);
    float*    sRed = (float*)(su + 24000);
    float*    sRedQ= (float*)(su + 24512);
    float*    sMean= (float*)(su + 25024);
    float*    sRstd= (float*)(su + 25088);

    int t = threadIdx.x, w = t >> 5, lane = t & 31;
    int g = lane >> 2, tig = lane & 3;
    int mr = w >> 3, wc = w & 7;
    int bid = blockIdx.x;
    int jt = bid & 3, i = (bid >> 2) & 255, b = bid >> 10;
    int j0 = jt * 64, bi = b * Nc + i;
    float mi = mask[bi];

    uint32_t sBsh = (uint32_t)__cvta_generic_to_shared(sB);

    #pragma unroll
    for (int c = 0; c < 2; c++) {
        int kr = t >> 6, c4 = t & 63;
        cp16(sBsh + (c * 2112 + kr * 264 + c4 * 4) * 4,
             g_W3t + (size_t)(c * 8 + kr) * INc + c4 * 4);
        CP_COMMIT;
    }

    #pragma unroll
    for (int u = 0; u < 8; u++) {
        int lin = u * 512 + t;
        int r = lin >> 6, c4 = lin & 63;
        float4 v = *(const float4*)(emb_edge +
            (((size_t)bi * Nc) + j0 + r) * INc + c4 * 4);
        float mm = mi * mask[b * Nc + j0 + r];
        uint4 dv;
        dv.x = f2tf(v.x * mm); dv.y = f2tf(v.y * mm);
        dv.z = f2tf(v.z * mm); dv.w = f2tf(v.w * mm);
        *(uint4*)(sA + r * 260 + c4 * 4) = dv;
    }
    if (t < 256) {
        sZ1[t] = g_z1[(size_t)bi * INc + t];
        sBE[t] = bedge[t]; sGA[t] = gamma_e[t]; sBT[t] = beta_e[t];
    }

    float acc[2][4][4];
    #pragma unroll
    for (int m = 0; m < 2; m++)
        #pragma unroll
        for (int n = 0; n < 4; n++)
            #pragma unroll
            for (int e = 0; e < 4; e++) acc[m][n][e] = 0.f;

    for (int c = 0; c < 32; c++) {
        CP_WAIT1;
        __syncthreads();
        if (c + 2 < 32) {
            int cc = c + 2;
            int kr = t >> 6, c4 = t & 63;
            cp16(sBsh + ((cc % 3) * 2112 + kr * 264 + c4 * 4) * 4,
                 g_W3t + (size_t)(cc * 8 + kr) * INc + c4 * 4);
            CP_COMMIT;
        }
        const uint32_t* Bb = sB + (c % 3) * 2112;
        int kc = c * 8;
        uint32_t af[2][4];
        #pragma unroll
        for (int mf = 0; mf < 2; mf++) {
            const uint32_t* Ar = sA + (mr * 32 + mf * 16 + g) * 260 + kc + tig;
            af[mf][0] = Ar[0];        af[mf][2] = Ar[4];
            af[mf][1] = Ar[8 * 260];  af[mf][3] = Ar[8 * 260 + 4];
        }
        #pragma unroll
        for (int n = 0; n < 4; n++) {
            int col = wc * 32 + n * 8 + g;
            uint32_t b0 = Bb[tig * 264 + col];
            uint32_t b1 = Bb[(tig + 4) * 264 + col];
            mma8(acc[0][n], af[0][0], af[0][1], af[0][2], af[0][3], b0, b1);
            mma8(acc[1][n], af[1][0], af[1][1], af[1][2], af[1][3], b0, b1);
        }
    }

    // ---- epilogue: residual + LayerNorm over 256 cols ----
    float vv[2][2][8];
    #pragma unroll
    for (int mf = 0; mf < 2; mf++) {
        #pragma unroll
        for (int rh = 0; rh < 2; rh++) {
            int r = mr * 32 + mf * 16 + g + 8 * rh;
            int j = j0 + r;
            float mm = mi * mask[b * Nc + j];
            const float* xerow = emb_edge + ((size_t)bi * Nc + j) * INc;
            const float* z2row = g_z2 + (size_t)(b * Nc + j) * INc;
            float sum = 0.f, sq = 0.f;
            #pragma unroll
            for (int n = 0; n < 4; n++) {
                int c0 = wc * 32 + n * 8 + 2 * tig;
                float2 xe2 = *(const float2*)(xerow + c0);
                float2 z22 = *(const float2*)(z2row + c0);
                float2 z12 = *(const float2*)(sZ1 + c0);
                float2 be2 = *(const float2*)(sBE + c0);
                float v0 = acc[mf][n][2 * rh]     + xe2.x * mm + z12.x + z22.x + be2.x;
                float v1 = acc[mf][n][2 * rh + 1] + xe2.y * mm + z12.y + z22.y + be2.y;
                vv[mf][rh][2 * n] = v0; vv[mf][rh][2 * n + 1] = v1;
                sum += v0 + v1;
                sq = fmaf(v0, v0, sq); sq = fmaf(v1, v1, sq);
            }
            sum += __shfl_xor_sync(0xffffffffu, sum, 1);
            sum += __shfl_xor_sync(0xffffffffu, sum, 2);
            sq  += __shfl_xor_sync(0xffffffffu, sq, 1);
            sq  += __shfl_xor_sync(0xffffffffu, sq, 2);
            if (tig == 0) { sRed[r * 8 + wc] = sum; sRedQ[r * 8 + wc] = sq; }
        }
    }
    __syncthreads();
    if (t < 64) {
        float s = 0.f, ss = 0.f;
        #pragma unroll
        for (int k = 0; k < 8; k++) { s += sRed[t * 8 + k]; ss += sRedQ[t * 8 + k]; }
        float mean = s * (1.f / 256.f);
        float var = ss * (1.f / 256.f) - mean * mean;
        sMean[t] = mean; sRstd[t] = rsqrtf(var + LN_EPS);
    }
    __syncthreads();
    #pragma unroll
    for (int mf = 0; mf < 2; mf++) {
        #pragma unroll
        for (int rh = 0; rh < 2; rh++) {
            int r = mr * 32 + mf * 16 + g + 8 * rh;
            int j = j0 + r;
            float mean = sMean[r], rs = sRstd[r];
            float* orow = out_edge + ((size_t)bi * Nc + j) * INc;
            #pragma unroll
            for (int n = 0; n < 4; n++) {
                int c0 = wc * 32 + n * 8 + 2 * tig;
                float2 ga2 = *(const float2*)(sGA + c0);
                float2 bt2 = *(const float2*)(sBT + c0);
                float2 o;
                o.x = (vv[mf][rh][2 * n]     - mean) * rs * ga2.x + bt2.x;
                o.y = (vv[mf][rh][2 * n + 1] - mean) * rs * ga2.y + bt2.y;
                *(float2*)(orow + c0) = o;
            }
        }
    }
}

// ============================================================
extern "C" void kernel_launch(void* const* d_in, const int* in_sizes, int n_in,
                              void* d_out, int out_size) {
    const float* emb_node = (const float*)d_in[0];
    const float* emb_edge = (const float*)d_in[1];
    const float* adj      = (const float*)d_in[2];
    const float* mask     = (const float*)d_in[3];
    const float* Ws       = (const float*)d_in[4];
    const float* Wt       = (const float*)d_in[5];
    const float* We       = (const float*)d_in[6];
    const float* attn     = (const float*)d_in[7];
    const float* Wn       = (const float*)d_in[8];
    const float* bn       = (const float*)d_in[9];
    const float* Wedge    = (const float*)d_in[10];
    const float* bedge    = (const float*)d_in[11];
    const float* gamma_x  = (const float*)d_in[12];
    const float* beta_x   = (const float*)d_in[13];
    const float* gamma_e  = (const float*)d_in[14];
    const float* beta_e   = (const float*)d_in[15];

    float* out_node = (float*)d_out;
    float* out_edge = out_node + Bc * Nc * INc;

    cudaFuncSetAttribute(k2_scores, cudaFuncAttributeMaxDynamicSharedMemorySize,
                         K2_SMEM_U * 4);
    cudaFuncSetAttribute(k4_fused, cudaFuncAttributeMaxDynamicSharedMemorySize,
                         K4_SMEM_U * 4);

    k0_wconv<<<384, 512>>>(We, Wedge);
    k1_nodes<<<dim3(64, 2), 512>>>(emb_node, mask, Ws, Wt);
    k2_scores<<<Bc * Nc * 4, 512, K2_SMEM_U * 4>>>(emb_edge, adj, mask, attn);
    k3_node<<<Bc * Nc, 256>>>(Wn, bn, Wedge, gamma_x, beta_x, out_node);
    k4_fused<<<Bc * Nc * 4, 512, K4_SMEM_U * 4>>>(emb_edge, mask, bedge,
                                                  gamma_e, beta_e, out_edge);
}

// round 4
// speedup vs baseline: 4.4692x; 1.2757x over previous
#include <cuda_runtime.h>
#include <cuda_fp16.h>
#include <math.h>
#include <stdint.h>

#define Bc   2
#define Nc   256
#define INc  256
#define Hc   8
#define Dc   64
#define HDc  512
#define ALPHA 0.2f
#define LN_EPS 1e-5f

// ---- scratch ----
__device__ float g_xn[Bc * Nc * INc];
__device__ float g_hs[Bc * Nc * HDc];
__device__ float g_ht[Bc * Nc * HDc];
__device__ float g_scores[(size_t)Bc * Nc * Nc * Hc];
__device__ float g_den[Bc * Nc * Hc];
__device__ float g_nn[Bc * Nc * Dc];
__device__ float g_z1[Bc * Nc * INc];
__device__ float g_z2[Bc * Nc * INc];
// fp16 weights, k-blocked (32-wide) n-major: [k>>5][n][k&31]
__device__ __half g_We16b[INc * HDc];
__device__ __half g_W316b[INc * INc];

__device__ __forceinline__ void mma16(float* c, const uint32_t* a,
                                      uint32_t b0, uint32_t b1) {
    asm volatile(
        "mma.sync.aligned.m16n8k16.row.col.f32.f16.f16.f32 "
        "{%0,%1,%2,%3},{%4,%5,%6,%7},{%8,%9},{%0,%1,%2,%3};\n"
        : "+f"(c[0]), "+f"(c[1]), "+f"(c[2]), "+f"(c[3])
        : "r"(a[0]), "r"(a[1]), "r"(a[2]), "r"(a[3]), "r"(b0), "r"(b1));
}
__device__ __forceinline__ void cp16(uint32_t dst, const void* src) {
    asm volatile("cp.async.cg.shared.global [%0], [%1], 16;\n" :: "r"(dst), "l"(src));
}
#define CP_COMMIT asm volatile("cp.async.commit_group;\n" ::)
#define CP_WAIT1  asm volatile("cp.async.wait_group 1;\n" ::)
#define CP_WAIT0  asm volatile("cp.async.wait_group 0;\n" ::)

// ============================================================
// K0: convert weights to fp16 blocked layout; zero g_den
// ============================================================
__global__ void k0_prep(const float* __restrict__ We,
                        const float* __restrict__ Wedge) {
    int i = blockIdx.x * 512 + threadIdx.x;
    if (i < INc * HDc) {
        int k = i >> 9, n = i & 511;
        g_We16b[(k >> 5) * (512 * 32) + n * 32 + (k & 31)] = __float2half(We[i]);
    }
    int j = i - INc * HDc;
    if (j >= 0 && j < INc * INc) {
        int k = j >> 8, n = j & 255;
        g_W316b[(k >> 5) * (256 * 32) + n * 32 + (k & 31)] =
            __float2half(Wedge[(size_t)(512 + k) * 256 + n]);
    }
    int m = i - (INc * HDc + INc * INc);
    if (m >= 0 && m < Bc * Nc * Hc) g_den[m] = 0.f;
}

// ============================================================
// K1: xn = emb_node*mask; h_{s,t} = xn @ W{s,t}. 16 rows/block.
// ============================================================
__global__ void k1_nodes(const float* __restrict__ emb_node,
                         const float* __restrict__ mask,
                         const float* __restrict__ Ws,
                         const float* __restrict__ Wt) {
    __shared__ float xs[16][INc];
    int t = threadIdx.x;
    int n0 = blockIdx.x * 16;
    const float* W  = blockIdx.y ? Wt : Ws;
    float* out      = blockIdx.y ? g_ht : g_hs;
    #pragma unroll
    for (int u = 0; u < 8; u++) {
        int lin = u * 512 + t;
        int r = lin >> 8, c = lin & 255;
        float v = emb_node[(size_t)(n0 + r) * INc + c] * mask[n0 + r];
        xs[r][c] = v;
        if (blockIdx.y == 0) g_xn[(size_t)(n0 + r) * INc + c] = v;
    }
    __syncthreads();
    float a[16];
    #pragma unroll
    for (int r = 0; r < 16; r++) a[r] = 0.f;
    #pragma unroll 4
    for (int k = 0; k < INc; k++) {
        float wv = W[(size_t)k * HDc + t];
        #pragma unroll
        for (int r = 0; r < 16; r++) a[r] = fmaf(xs[r][k], wv, a[r]);
    }
    #pragma unroll
    for (int r = 0; r < 16; r++)
        out[(size_t)(n0 + r) * HDc + t] = a[r];
}

// ============================================================
// K2: fp16 scores kernel. 512 threads, 16 warps.
// C 64x512, K=256 in 8 k32 chunks. Warp tile 32x64.
// SMEM u32: A[64][132]=8448 | B 3x[512][20]=30720 | hs 512 | at 512
// Fuses denominator atomicAdd into epilogue.
// ============================================================
#define K2_SMEM_B ((8448 + 30720 + 512 + 512) * 4)
__global__ void __launch_bounds__(512, 1)
k2_scores(const float* __restrict__ emb_edge,
          const float* __restrict__ adj,
          const float* __restrict__ mask,
          const float* __restrict__ attn) {
    extern __shared__ uint32_t su[];
    uint32_t* sA  = su;              // halves, row pitch 264 (132 u32)
    uint32_t* sB  = su + 8448;       // 3 stages, n-major pitch 40 halves
    float*    sHS = (float*)(su + 39168);
    float*    sAT = (float*)(su + 39680);

    int t = threadIdx.x, w = t >> 5, lane = t & 31;
    int g = lane >> 2, tig = lane & 3;
    int mr = w >> 3, wc = w & 7;
    int bid = blockIdx.x;
    int jt = bid & 3, i = (bid >> 2) & 255, b = bid >> 10;
    int j0 = jt * 64, bi = b * Nc + i;
    float mi = mask[bi];

    uint32_t sBsh = (uint32_t)__cvta_generic_to_shared(sB);

    // prefetch B chunks 0,1 (each 512n x 32k halves = 32KB contiguous)
    #pragma unroll
    for (int c = 0; c < 2; c++) {
        #pragma unroll
        for (int q = 0; q < 4; q++) {
            int t8 = q * 512 + t;
            int n = t8 >> 2, kq = t8 & 3;
            cp16(sBsh + (c * 10240 + n * 20 + kq * 4) * 4,
                 g_We16b + (size_t)c * 16384 + (size_t)t8 * 8);
        }
        CP_COMMIT;
    }

    // stage A (masked xe -> fp16)
    #pragma unroll
    for (int u = 0; u < 8; u++) {
        int lin = u * 512 + t;
        int r = lin >> 6, c4 = lin & 63;
        float4 v = *(const float4*)(emb_edge +
            (((size_t)bi * Nc) + j0 + r) * INc + c4 * 4);
        float mm = mi * mask[b * Nc + j0 + r];
        __half2 h01 = __floats2half2_rn(v.x * mm, v.y * mm);
        __half2 h23 = __floats2half2_rn(v.z * mm, v.w * mm);
        uint32_t* dst = sA + r * 132 + c4 * 2;
        dst[0] = *reinterpret_cast<uint32_t*>(&h01);
        dst[1] = *reinterpret_cast<uint32_t*>(&h23);
    }
    sHS[t] = g_hs[(size_t)bi * HDc + t];
    sAT[t] = attn[t];

    float acc[2][8][4];
    #pragma unroll
    for (int m = 0; m < 2; m++)
        #pragma unroll
        for (int n = 0; n < 8; n++)
            #pragma unroll
            for (int e = 0; e < 4; e++) acc[m][n][e] = 0.f;

    for (int c = 0; c < 8; c++) {
        if (c < 7) { CP_WAIT1; } else { CP_WAIT0; }
        __syncthreads();
        if (c + 2 < 8) {
            int cc = c + 2;
            #pragma unroll
            for (int q = 0; q < 4; q++) {
                int t8 = q * 512 + t;
                int n = t8 >> 2, kq = t8 & 3;
                cp16(sBsh + ((cc % 3) * 10240 + n * 20 + kq * 4) * 4,
                     g_We16b + (size_t)cc * 16384 + (size_t)t8 * 8);
            }
            CP_COMMIT;
        }
        const uint32_t* Bb = sB + (c % 3) * 10240;
        #pragma unroll
        for (int kk = 0; kk < 2; kk++) {
            int ku = c * 16 + kk * 8;
            uint32_t af[2][4];
            #pragma unroll
            for (int mf = 0; mf < 2; mf++) {
                const uint32_t* Ar = sA + (mr * 32 + mf * 16 + g) * 132 + ku + tig;
                af[mf][0] = Ar[0];        af[mf][2] = Ar[4];
                af[mf][1] = Ar[8 * 132];  af[mf][3] = Ar[8 * 132 + 4];
            }
            #pragma unroll
            for (int n = 0; n < 8; n++) {
                int col = wc * 64 + n * 8 + g;
                uint32_t b0 = Bb[col * 20 + kk * 8 + tig];
                uint32_t b1 = Bb[col * 20 + kk * 8 + tig + 4];
                mma16(acc[0][n], af[0], b0, b1);
                mma16(acc[1][n], af[1], b0, b1);
            }
        }
    }

    // ---- epilogue: lrelu + attn-dot + exp + denom atomics ----
    float wsum = 0.f;
    #pragma unroll
    for (int mf = 0; mf < 2; mf++) {
        #pragma unroll
        for (int rh = 0; rh < 2; rh++) {
            int j = j0 + mr * 32 + mf * 16 + g + 8 * rh;
            const float* htrow = g_ht + (size_t)(b * Nc + j) * HDc + wc * 64;
            float sum = 0.f;
            #pragma unroll
            for (int n = 0; n < 8; n++) {
                int c0 = n * 8 + 2 * tig;
                float2 hte = *(const float2*)(htrow + c0);
                float2 hs2 = *(const float2*)(sHS + wc * 64 + c0);
                float2 at2 = *(const float2*)(sAT + wc * 64 + c0);
                float v0 = acc[mf][n][2 * rh]     + hs2.x + hte.x;
                float v1 = acc[mf][n][2 * rh + 1] + hs2.y + hte.y;
                v0 = v0 > 0.f ? v0 : ALPHA * v0;
                v1 = v1 > 0.f ? v1 : ALPHA * v1;
                sum = fmaf(at2.x, v0, sum);
                sum = fmaf(at2.y, v1, sum);
            }
            sum += __shfl_xor_sync(0xffffffffu, sum, 1);
            sum += __shfl_xor_sync(0xffffffffu, sum, 2);
            if (tig == 0) {
                size_t e = (size_t)bi * Nc + j;
                float sv = expf(sum) * adj[e] * (mi * mask[b * Nc + j]);
                g_scores[e * 8 + wc] = sv;
                wsum += sv;
            }
        }
    }
    wsum += __shfl_xor_sync(0xffffffffu, wsum, 4);
    wsum += __shfl_xor_sync(0xffffffffu, wsum, 8);
    wsum += __shfl_xor_sync(0xffffffffu, wsum, 16);
    if (lane == 0) atomicAdd(&g_den[bi * 8 + wc], wsum);
}

// ============================================================
// K3b: new_node einsum. Block = (8 i rows, batch b). 512 thr.
// Thread (js = t>>6, d = t&63): partial over j slice, all 8 rows.
// SMEM f32: s[8][2048]=16384 | inv[64] | red[8*8*64]=4096
// ============================================================
#define K3B_SMEM_B ((16384 + 64 + 4096) * 4)
__global__ void __launch_bounds__(512, 1) k3b_newnode() {
    extern __shared__ float smf[];
    float* s_sh = smf;            // [r][jh] pitch 2048
    float* inv  = smf + 16384;
    float* redn = smf + 16448;    // [js][r][d]

    int t = threadIdx.x;
    int b = blockIdx.y, i0 = blockIdx.x * 8, bi0 = b * Nc + i0;

    if (t < 64) {
        int r = t >> 3, h = t & 7;
        inv[t] = 1.f / (g_den[(bi0 + r) * 8 + h] + 1e-6f);
    }
    __syncthreads();
    #pragma unroll
    for (int u = 0; u < 32; u++) {
        int lin = u * 512 + t;
        int r = lin >> 11, jh = lin & 2047;
        s_sh[r * 2048 + jh] =
            g_scores[(size_t)(bi0 + r) * 2048 + jh] * inv[r * 8 + (jh & 7)];
    }
    __syncthreads();

    int js = t >> 6, d = t & 63;
    float a[8];
    #pragma unroll
    for (int r = 0; r < 8; r++) a[r] = 0.f;
    const float* htb = g_ht + (size_t)b * Nc * HDc;
    for (int j = js * 32; j < js * 32 + 32; j++) {
        const float* hp = htb + (size_t)j * HDc + d;
        #pragma unroll
        for (int h = 0; h < 8; h++) {
            float htv = hp[h * 64];
            #pragma unroll
            for (int r = 0; r < 8; r++)
                a[r] = fmaf(s_sh[r * 2048 + j * 8 + h], htv, a[r]);
        }
    }
    #pragma unroll
    for (int r = 0; r < 8; r++) redn[js * 512 + r * 64 + d] = a[r];
    __syncthreads();
    {
        int r = t >> 6, dd = t & 63;
        float s = 0.f;
        #pragma unroll
        for (int q = 0; q < 8; q++) s += redn[q * 512 + r * 64 + dd];
        g_nn[(size_t)(bi0 + r) * Dc + dd] = s;
    }
}

// ============================================================
// K3c: np = nn@Wn + bn; node LN; z1/z2 projections. 8 nodes/block.
// ============================================================
__global__ void __launch_bounds__(512, 1)
k3c_node(const float* __restrict__ Wn,
         const float* __restrict__ bn,
         const float* __restrict__ Wedge,
         const float* __restrict__ gamma_x,
         const float* __restrict__ beta_x,
         float* __restrict__ out_node) {
    __shared__ float nn_sh[8][Dc];
    __shared__ float np_sh[8][INc];
    __shared__ float vsh[8][INc];
    __shared__ float mean_sh[8], rstd_sh[8];
    int t = threadIdx.x, w = t >> 5, lane = t & 31;
    int bi0 = blockIdx.x * 8;

    if (t < 512) {
        int r = t >> 6, d = t & 63;
        nn_sh[r][d] = g_nn[(size_t)(bi0 + r) * Dc + d];
    }
    __syncthreads();

    int c = t & 255, rp = t >> 8;   // rp in {0,1} -> rows rp*4..rp*4+3
    float np[4];
    #pragma unroll
    for (int rr = 0; rr < 4; rr++) np[rr] = bn[c];
    #pragma unroll 4
    for (int d = 0; d < Dc; d++) {
        float wv = Wn[(size_t)d * INc + c];
        #pragma unroll
        for (int rr = 0; rr < 4; rr++)
            np[rr] = fmaf(nn_sh[rp * 4 + rr][d], wv, np[rr]);
    }
    #pragma unroll
    for (int rr = 0; rr < 4; rr++) {
        int r = rp * 4 + rr;
        np_sh[r][c] = np[rr];
        vsh[r][c] = g_xn[(size_t)(bi0 + r) * INc + c] + np[rr];
    }
    __syncthreads();
    if (w < 8) {
        float s = 0.f, sq = 0.f;
        #pragma unroll
        for (int u = 0; u < 8; u++) {
            float v = vsh[w][lane + u * 32];
            s += v; sq = fmaf(v, v, sq);
        }
        #pragma unroll
        for (int off = 16; off > 0; off >>= 1) {
            s  += __shfl_xor_sync(0xffffffffu, s, off);
            sq += __shfl_xor_sync(0xffffffffu, sq, off);
        }
        if (lane == 0) {
            float mean = s * (1.f / 256.f);
            mean_sh[w] = mean;
            rstd_sh[w] = rsqrtf(sq * (1.f / 256.f) - mean * mean + LN_EPS);
        }
    }
    __syncthreads();
    #pragma unroll
    for (int rr = 0; rr < 4; rr++) {
        int r = rp * 4 + rr;
        out_node[(size_t)(bi0 + r) * INc + c] =
            (vsh[r][c] - mean_sh[r]) * rstd_sh[r] * gamma_x[c] + beta_x[c];
    }
    // z1/z2 projections
    float z1a[4] = {0.f, 0.f, 0.f, 0.f}, z2a[4] = {0.f, 0.f, 0.f, 0.f};
    #pragma unroll 2
    for (int k = 0; k < INc; k++) {
        float w1 = Wedge[(size_t)k * INc + c];
        float w2 = Wedge[(size_t)(k + 256) * INc + c];
        #pragma unroll
        for (int rr = 0; rr < 4; rr++) {
            float npv = np_sh[rp * 4 + rr][k];
            z1a[rr] = fmaf(npv, w1, z1a[rr]);
            z2a[rr] = fmaf(npv, w2, z2a[rr]);
        }
    }
    #pragma unroll
    for (int rr = 0; rr < 4; rr++) {
        int r = rp * 4 + rr;
        g_z1[(size_t)(bi0 + r) * INc + c] = z1a[rr];
        g_z2[(size_t)(bi0 + r) * INc + c] = z2a[rr];
    }
}

// ============================================================
// K4: fp16 z3 GEMM + residual + LayerNorm. 512 threads.
// C 64x256, K=256 in 8 k32 chunks. Warp tile 32x32.
// SMEM u32: A[64][132]=8448 | B 3x[256][20]=15360 | z1/be/ga/bt
//           4x256 | red 512 | redq 512 | mean 64 | rstd 64
// ============================================================
#define K4_SMEM_B ((8448 + 15360 + 1024 + 512 + 512 + 64 + 64) * 4)
__global__ void __launch_bounds__(512, 1)
k4_fused(const float* __restrict__ emb_edge,
         const float* __restrict__ mask,
         const float* __restrict__ bedge,
         const float* __restrict__ gamma_e,
         const float* __restrict__ beta_e,
         float* __restrict__ out_edge) {
    extern __shared__ uint32_t su[];
    uint32_t* sA   = su;
    uint32_t* sB   = su + 8448;
    float*    sZ1  = (float*)(su + 23808);
    float*    sBE  = (float*)(su + 24064);
    float*    sGA  = (float*)(su + 24320);
    float*    sBT  = (float*)(su + 24576);
    float*    sRed = (float*)(su + 24832);
    float*    sRedQ= (float*)(su + 25344);
    float*    sMean= (float*)(su + 25856);
    float*    sRstd= (float*)(su + 25920);

    int t = threadIdx.x, w = t >> 5, lane = t & 31;
    int g = lane >> 2, tig = lane & 3;
    int mr = w >> 3, wc = w & 7;
    int bid = blockIdx.x;
    int jt = bid & 3, i = (bid >> 2) & 255, b = bid >> 10;
    int j0 = jt * 64, bi = b * Nc + i;
    float mi = mask[bi];

    uint32_t sBsh = (uint32_t)__cvta_generic_to_shared(sB);

    #pragma unroll
    for (int c = 0; c < 2; c++) {
        #pragma unroll
        for (int q = 0; q < 2; q++) {
            int t8 = q * 512 + t;
            int n = t8 >> 2, kq = t8 & 3;
            cp16(sBsh + (c * 5120 + n * 20 + kq * 4) * 4,
                 g_W316b + (size_t)c * 8192 + (size_t)t8 * 8);
        }
        CP_COMMIT;
    }

    #pragma unroll
    for (int u = 0; u < 8; u++) {
        int lin = u * 512 + t;
        int r = lin >> 6, c4 = lin & 63;
        float4 v = *(const float4*)(emb_edge +
            (((size_t)bi * Nc) + j0 + r) * INc + c4 * 4);
        float mm = mi * mask[b * Nc + j0 + r];
        __half2 h01 = __floats2half2_rn(v.x * mm, v.y * mm);
        __half2 h23 = __floats2half2_rn(v.z * mm, v.w * mm);
        uint32_t* dst = sA + r * 132 + c4 * 2;
        dst[0] = *reinterpret_cast<uint32_t*>(&h01);
        dst[1] = *reinterpret_cast<uint32_t*>(&h23);
    }
    if (t < 256) {
        sZ1[t] = g_z1[(size_t)bi * INc + t];
        sBE[t] = bedge[t]; sGA[t] = gamma_e[t]; sBT[t] = beta_e[t];
    }

    float acc[2][4][4];
    #pragma unroll
    for (int m = 0; m < 2; m++)
        #pragma unroll
        for (int n = 0; n < 4; n++)
            #pragma unroll
            for (int e = 0; e < 4; e++) acc[m][n][e] = 0.f;

    for (int c = 0; c < 8; c++) {
        if (c < 7) { CP_WAIT1; } else { CP_WAIT0; }
        __syncthreads();
        if (c + 2 < 8) {
            int cc = c + 2;
            #pragma unroll
            for (int q = 0; q < 2; q++) {
                int t8 = q * 512 + t;
                int n = t8 >> 2, kq = t8 & 3;
                cp16(sBsh + ((cc % 3) * 5120 + n * 20 + kq * 4) * 4,
                     g_W316b + (size_t)cc * 8192 + (size_t)t8 * 8);
            }
            CP_COMMIT;
        }
        const uint32_t* Bb = sB + (c % 3) * 5120;
        #pragma unroll
        for (int kk = 0; kk < 2; kk++) {
            int ku = c * 16 + kk * 8;
            uint32_t af[2][4];
            #pragma unroll
            for (int mf = 0; mf < 2; mf++) {
                const uint32_t* Ar = sA + (mr * 32 + mf * 16 + g) * 132 + ku + tig;
                af[mf][0] = Ar[0];        af[mf][2] = Ar[4];
                af[mf][1] = Ar[8 * 132];  af[mf][3] = Ar[8 * 132 + 4];
            }
            #pragma unroll
            for (int n = 0; n < 4; n++) {
                int col = wc * 32 + n * 8 + g;
                uint32_t b0 = Bb[col * 20 + kk * 8 + tig];
                uint32_t b1 = Bb[col * 20 + kk * 8 + tig + 4];
                mma16(acc[0][n], af[0], b0, b1);
                mma16(acc[1][n], af[1], b0, b1);
            }
        }
    }

    // ---- epilogue: residual + LayerNorm over 256 cols ----
    float vv[2][2][8];
    #pragma unroll
    for (int mf = 0; mf < 2; mf++) {
        #pragma unroll
        for (int rh = 0; rh < 2; rh++) {
            int r = mr * 32 + mf * 16 + g + 8 * rh;
            int j = j0 + r;
            float mm = mi * mask[b * Nc + j];
            const float* xerow = emb_edge + ((size_t)bi * Nc + j) * INc;
            const float* z2row = g_z2 + (size_t)(b * Nc + j) * INc;
            float sum = 0.f, sq = 0.f;
            #pragma unroll
            for (int n = 0; n < 4; n++) {
                int c0 = wc * 32 + n * 8 + 2 * tig;
                float2 xe2 = *(const float2*)(xerow + c0);
                float2 z22 = *(const float2*)(z2row + c0);
                float2 z12 = *(const float2*)(sZ1 + c0);
                float2 be2 = *(const float2*)(sBE + c0);
                float v0 = acc[mf][n][2 * rh]     + xe2.x * mm + z12.x + z22.x + be2.x;
                float v1 = acc[mf][n][2 * rh + 1] + xe2.y * mm + z12.y + z22.y + be2.y;
                vv[mf][rh][2 * n] = v0; vv[mf][rh][2 * n + 1] = v1;
                sum += v0 + v1;
                sq = fmaf(v0, v0, sq); sq = fmaf(v1, v1, sq);
            }
            sum += __shfl_xor_sync(0xffffffffu, sum, 1);
            sum += __shfl_xor_sync(0xffffffffu, sum, 2);
            sq  += __shfl_xor_sync(0xffffffffu, sq, 1);
            sq  += __shfl_xor_sync(0xffffffffu, sq, 2);
            if (tig == 0) { sRed[r * 8 + wc] = sum; sRedQ[r * 8 + wc] = sq; }
        }
    }
    __syncthreads();
    if (t < 64) {
        float s = 0.f, ss = 0.f;
        #pragma unroll
        for (int k = 0; k < 8; k++) { s += sRed[t * 8 + k]; ss += sRedQ[t * 8 + k]; }
        float mean = s * (1.f / 256.f);
        float var = ss * (1.f / 256.f) - mean * mean;
        sMean[t] = mean; sRstd[t] = rsqrtf(var + LN_EPS);
    }
    __syncthreads();
    #pragma unroll
    for (int mf = 0; mf < 2; mf++) {
        #pragma unroll
        for (int rh = 0; rh < 2; rh++) {
            int r = mr * 32 + mf * 16 + g + 8 * rh;
            int j = j0 + r;
            float mean = sMean[r], rs = sRstd[r];
            float* orow = out_edge + ((size_t)bi * Nc + j) * INc;
            #pragma unroll
            for (int n = 0; n < 4; n++) {
                int c0 = wc * 32 + n * 8 + 2 * tig;
                float2 ga2 = *(const float2*)(sGA + c0);
                float2 bt2 = *(const float2*)(sBT + c0);
                float2 o;
                o.x = (vv[mf][rh][2 * n]     - mean) * rs * ga2.x + bt2.x;
                o.y = (vv[mf][rh][2 * n + 1] - mean) * rs * ga2.y + bt2.y;
                *(float2*)(orow + c0) = o;
            }
        }
    }
}

// ============================================================
extern "C" void kernel_launch(void* const* d_in, const int* in_sizes, int n_in,
                              void* d_out, int out_size) {
    const float* emb_node = (const float*)d_in[0];
    const float* emb_edge = (const float*)d_in[1];
    const float* adj      = (const float*)d_in[2];
    const float* mask     = (const float*)d_in[3];
    const float* Ws       = (const float*)d_in[4];
    const float* Wt       = (const float*)d_in[5];
    const float* We       = (const float*)d_in[6];
    const float* attn     = (const float*)d_in[7];
    const float* Wn       = (const float*)d_in[8];
    const float* bn       = (const float*)d_in[9];
    const float* Wedge    = (const float*)d_in[10];
    const float* bedge    = (const float*)d_in[11];
    const float* gamma_x  = (const float*)d_in[12];
    const float* beta_x   = (const float*)d_in[13];
    const float* gamma_e  = (const float*)d_in[14];
    const float* beta_e   = (const float*)d_in[15];

    float* out_node = (float*)d_out;
    float* out_edge = out_node + Bc * Nc * INc;

    cudaFuncSetAttribute(k2_scores, cudaFuncAttributeMaxDynamicSharedMemorySize,
                         K2_SMEM_B);
    cudaFuncSetAttribute(k3b_newnode, cudaFuncAttributeMaxDynamicSharedMemorySize,
                         K3B_SMEM_B);
    cudaFuncSetAttribute(k4_fused, cudaFuncAttributeMaxDynamicSharedMemorySize,
                         K4_SMEM_B);

    k0_prep<<<392, 512>>>(We, Wedge);
    k1_nodes<<<dim3(32, 2), 512>>>(emb_node, mask, Ws, Wt);
    k2_scores<<<Bc * Nc * 4, 512, K2_SMEM_B>>>(emb_edge, adj, mask, attn);
    k3b_newnode<<<dim3(32, 2), 512, K3B_SMEM_B>>>();
    k3c_node<<<64, 512>>>(Wn, bn, Wedge, gamma_x, beta_x, out_node);
    k4_fused<<<Bc * Nc * 4, 512, K4_SMEM_B>>>(emb_edge, mask, bedge,
                                              gamma_e, beta_e, out_edge);
}

// round 5
// speedup vs baseline: 4.4823x; 1.0029x over previous
#include <cuda_runtime.h>
#include <cuda_fp16.h>
#include <math.h>
#include <stdint.h>

#define Bc   2
#define Nc   256
#define INc  256
#define Hc   8
#define Dc   64
#define HDc  512
#define ALPHA 0.2f
#define LN_EPS 1e-5f

// ---- scratch ----
__device__ float g_xn[Bc * Nc * INc];
__device__ float g_hs[Bc * Nc * HDc];
__device__ float g_ht[Bc * Nc * HDc];
__device__ float g_scores[(size_t)Bc * Nc * Nc * Hc];
__device__ float g_den[Bc * Nc * Hc];
__device__ float g_nn[Bc * Nc * Dc];
__device__ float g_z1[Bc * Nc * INc];
__device__ float g_z2[Bc * Nc * INc];
// fp16 weights, k-blocked (32-wide) n-major: [k>>5][n][k&31]
__device__ __half g_We16b[INc * HDc];
__device__ __half g_W316b[INc * INc];

__device__ __forceinline__ void mma16(float* c, const uint32_t* a,
                                      uint32_t b0, uint32_t b1) {
    asm volatile(
        "mma.sync.aligned.m16n8k16.row.col.f32.f16.f16.f32 "
        "{%0,%1,%2,%3},{%4,%5,%6,%7},{%8,%9},{%0,%1,%2,%3};\n"
        : "+f"(c[0]), "+f"(c[1]), "+f"(c[2]), "+f"(c[3])
        : "r"(a[0]), "r"(a[1]), "r"(a[2]), "r"(a[3]), "r"(b0), "r"(b1));
}
__device__ __forceinline__ void ldsm4(uint32_t* r, uint32_t addr) {
    asm volatile("ldmatrix.sync.aligned.m8n8.x4.shared.b16 {%0,%1,%2,%3}, [%4];\n"
        : "=r"(r[0]), "=r"(r[1]), "=r"(r[2]), "=r"(r[3]) : "r"(addr));
}
__device__ __forceinline__ void cp16(uint32_t dst, const void* src) {
    asm volatile("cp.async.cg.shared.global [%0], [%1], 16;\n" :: "r"(dst), "l"(src));
}
#define CP_COMMIT asm volatile("cp.async.commit_group;\n" ::)
#define CP_WAIT1  asm volatile("cp.async.wait_group 1;\n" ::)
#define CP_WAIT0  asm volatile("cp.async.wait_group 0;\n" ::)

// ============================================================
// K0: convert weights to fp16 blocked layout; zero g_den
// ============================================================
__global__ void k0_prep(const float* __restrict__ We,
                        const float* __restrict__ Wedge) {
    int i = blockIdx.x * 512 + threadIdx.x;
    if (i < INc * HDc) {
        int k = i >> 9, n = i & 511;
        g_We16b[(k >> 5) * (512 * 32) + n * 32 + (k & 31)] = __float2half(We[i]);
    }
    int j = i - INc * HDc;
    if (j >= 0 && j < INc * INc) {
        int k = j >> 8, n = j & 255;
        g_W316b[(k >> 5) * (256 * 32) + n * 32 + (k & 31)] =
            __float2half(Wedge[(size_t)(512 + k) * 256 + n]);
    }
    int m = i - (INc * HDc + INc * INc);
    if (m >= 0 && m < Bc * Nc * Hc) g_den[m] = 0.f;
}

// ============================================================
// K1: xn = emb_node*mask; h_{s,t} = xn @ W{s,t}. 16 rows/block.
// ============================================================
__global__ void k1_nodes(const float* __restrict__ emb_node,
                         const float* __restrict__ mask,
                         const float* __restrict__ Ws,
                         const float* __restrict__ Wt) {
    __shared__ float xs[16][INc];
    int t = threadIdx.x;
    int n0 = blockIdx.x * 16;
    const float* W  = blockIdx.y ? Wt : Ws;
    float* out      = blockIdx.y ? g_ht : g_hs;
    #pragma unroll
    for (int u = 0; u < 8; u++) {
        int lin = u * 512 + t;
        int r = lin >> 8, c = lin & 255;
        float v = emb_node[(size_t)(n0 + r) * INc + c] * mask[n0 + r];
        xs[r][c] = v;
        if (blockIdx.y == 0) g_xn[(size_t)(n0 + r) * INc + c] = v;
    }
    __syncthreads();
    float a[16];
    #pragma unroll
    for (int r = 0; r < 16; r++) a[r] = 0.f;
    #pragma unroll 4
    for (int k = 0; k < INc; k++) {
        float wv = W[(size_t)k * HDc + t];
        #pragma unroll
        for (int r = 0; r < 16; r++) a[r] = fmaf(xs[r][k], wv, a[r]);
    }
    #pragma unroll
    for (int r = 0; r < 16; r++)
        out[(size_t)(n0 + r) * HDc + t] = a[r];
}

// ============================================================
// K2: fp16 scores kernel. 256 threads, 8 warps.
// Block tile 64x512, K=256 (8 k32 chunks). Warp tile 64x64:
// warp w = col group wc, all 4 row groups (mf). ldmatrix loads.
// SMEM u32: A[64][132]=8448 | B 3x[512][20]=30720 | hs 512 | at 512
// ============================================================
#define K2_SMEM_B ((8448 + 30720 + 512 + 512) * 4)
__global__ void __launch_bounds__(256, 1)
k2_scores(const float* __restrict__ emb_edge,
          const float* __restrict__ adj,
          const float* __restrict__ mask,
          const float* __restrict__ attn) {
    extern __shared__ uint32_t su[];
    uint32_t* sA  = su;              // halves, row pitch 264 (132 u32)
    uint32_t* sB  = su + 8448;       // 3 stages, n-major pitch 40 halves
    float*    sHS = (float*)(su + 39168);
    float*    sAT = (float*)(su + 39680);

    int t = threadIdx.x, wc = t >> 5, lane = t & 31;
    int g = lane >> 2, tig = lane & 3;
    int lm = lane & 7, lq = lane >> 3;
    int bid = blockIdx.x;
    int jt = bid & 3, i = (bid >> 2) & 255, b = bid >> 10;
    int j0 = jt * 64, bi = b * Nc + i;
    float mi = mask[bi];

    uint32_t sAsh = (uint32_t)__cvta_generic_to_shared(sA);
    uint32_t sBsh = (uint32_t)__cvta_generic_to_shared(sB);

    // prefetch B chunks 0,1 (each 512n x 32k halves)
    #pragma unroll
    for (int c = 0; c < 2; c++) {
        #pragma unroll
        for (int q = 0; q < 8; q++) {
            int t8 = q * 256 + t;
            int n = t8 >> 2, kq = t8 & 3;
            cp16(sBsh + (c * 10240 + n * 20 + kq * 4) * 4,
                 g_We16b + (size_t)c * 16384 + (size_t)t8 * 8);
        }
        CP_COMMIT;
    }

    // stage A (masked xe -> fp16)
    #pragma unroll
    for (int u = 0; u < 16; u++) {
        int lin = u * 256 + t;
        int r = lin >> 6, c4 = lin & 63;
        float4 v = *(const float4*)(emb_edge +
            (((size_t)bi * Nc) + j0 + r) * INc + c4 * 4);
        float mm = mi * mask[b * Nc + j0 + r];
        __half2 h01 = __floats2half2_rn(v.x * mm, v.y * mm);
        __half2 h23 = __floats2half2_rn(v.z * mm, v.w * mm);
        uint32_t* dst = sA + r * 132 + c4 * 2;
        dst[0] = *reinterpret_cast<uint32_t*>(&h01);
        dst[1] = *reinterpret_cast<uint32_t*>(&h23);
    }
    #pragma unroll
    for (int u = 0; u < 2; u++) {
        sHS[u * 256 + t] = g_hs[(size_t)bi * HDc + u * 256 + t];
        sAT[u * 256 + t] = attn[u * 256 + t];
    }

    // ldmatrix per-lane address components
    int aRow = lm + (lq & 1) * 8;          // + mf*16
    int aCol = (lq >> 1) * 8;              // + kh (halves)
    int bRow = wc * 64 + (lq >> 1) * 8 + lm;  // + p*16
    int bCol = (lq & 1) * 8;               // + kk*16 (halves)

    float acc[4][8][4];
    #pragma unroll
    for (int m = 0; m < 4; m++)
        #pragma unroll
        for (int n = 0; n < 8; n++)
            #pragma unroll
            for (int e = 0; e < 4; e++) acc[m][n][e] = 0.f;

    for (int c = 0; c < 8; c++) {
        if (c < 7) { CP_WAIT1; } else { CP_WAIT0; }
        __syncthreads();
        if (c + 2 < 8) {
            int cc = c + 2;
            #pragma unroll
            for (int q = 0; q < 8; q++) {
                int t8 = q * 256 + t;
                int n = t8 >> 2, kq = t8 & 3;
                cp16(sBsh + ((cc % 3) * 10240 + n * 20 + kq * 4) * 4,
                     g_We16b + (size_t)cc * 16384 + (size_t)t8 * 8);
            }
            CP_COMMIT;
        }
        uint32_t stOff = sBsh + (c % 3) * 40960;
        #pragma unroll
        for (int kk = 0; kk < 2; kk++) {
            int kh = c * 32 + kk * 16;
            uint32_t af[4][4];
            #pragma unroll
            for (int mf = 0; mf < 4; mf++)
                ldsm4(af[mf], sAsh + ((mf * 16 + aRow) * 264 + kh + aCol) * 2);
            #pragma unroll
            for (int p = 0; p < 4; p++) {
                uint32_t bf[4];
                ldsm4(bf, stOff + ((bRow + p * 16) * 40 + kk * 16 + bCol) * 2);
                #pragma unroll
                for (int mf = 0; mf < 4; mf++) {
                    mma16(acc[mf][2 * p],     af[mf], bf[0], bf[1]);
                    mma16(acc[mf][2 * p + 1], af[mf], bf[2], bf[3]);
                }
            }
        }
    }

    // ---- epilogue: lrelu + attn-dot + exp + denom atomics ----
    float wsum = 0.f;
    #pragma unroll
    for (int mf = 0; mf < 4; mf++) {
        #pragma unroll
        for (int rh = 0; rh < 2; rh++) {
            int j = j0 + mf * 16 + g + 8 * rh;
            const float* htrow = g_ht + (size_t)(b * Nc + j) * HDc + wc * 64;
            float sum = 0.f;
            #pragma unroll
            for (int n = 0; n < 8; n++) {
                int c0 = n * 8 + 2 * tig;
                float2 hte = *(const float2*)(htrow + c0);
                float2 hs2 = *(const float2*)(sHS + wc * 64 + c0);
                float2 at2 = *(const float2*)(sAT + wc * 64 + c0);
                float v0 = acc[mf][n][2 * rh]     + hs2.x + hte.x;
                float v1 = acc[mf][n][2 * rh + 1] + hs2.y + hte.y;
                v0 = v0 > 0.f ? v0 : ALPHA * v0;
                v1 = v1 > 0.f ? v1 : ALPHA * v1;
                sum = fmaf(at2.x, v0, sum);
                sum = fmaf(at2.y, v1, sum);
            }
            sum += __shfl_xor_sync(0xffffffffu, sum, 1);
            sum += __shfl_xor_sync(0xffffffffu, sum, 2);
            if (tig == 0) {
                size_t e = (size_t)bi * Nc + j;
                float sv = expf(sum) * adj[e] * (mi * mask[b * Nc + j]);
                g_scores[e * 8 + wc] = sv;
                wsum += sv;
            }
        }
    }
    wsum += __shfl_xor_sync(0xffffffffu, wsum, 4);
    wsum += __shfl_xor_sync(0xffffffffu, wsum, 8);
    wsum += __shfl_xor_sync(0xffffffffu, wsum, 16);
    if (lane == 0) atomicAdd(&g_den[bi * 8 + wc], wsum);
}

// ============================================================
// K3b: new_node einsum. Block = (8 i rows, batch b). 512 thr.
// ============================================================
#define K3B_SMEM_B ((16384 + 64 + 4096) * 4)
__global__ void __launch_bounds__(512, 1) k3b_newnode() {
    extern __shared__ float smf[];
    float* s_sh = smf;            // [r][jh] pitch 2048
    float* inv  = smf + 16384;
    float* redn = smf + 16448;    // [js][r][d]

    int t = threadIdx.x;
    int b = blockIdx.y, i0 = blockIdx.x * 8, bi0 = b * Nc + i0;

    if (t < 64) {
        int r = t >> 3, h = t & 7;
        inv[t] = 1.f / (g_den[(bi0 + r) * 8 + h] + 1e-6f);
    }
    __syncthreads();
    #pragma unroll
    for (int u = 0; u < 32; u++) {
        int lin = u * 512 + t;
        int r = lin >> 11, jh = lin & 2047;
        s_sh[r * 2048 + jh] =
            g_scores[(size_t)(bi0 + r) * 2048 + jh] * inv[r * 8 + (jh & 7)];
    }
    __syncthreads();

    int js = t >> 6, d = t & 63;
    float a[8];
    #pragma unroll
    for (int r = 0; r < 8; r++) a[r] = 0.f;
    const float* htb = g_ht + (size_t)b * Nc * HDc;
    for (int j = js * 32; j < js * 32 + 32; j++) {
        const float* hp = htb + (size_t)j * HDc + d;
        #pragma unroll
        for (int h = 0; h < 8; h++) {
            float htv = hp[h * 64];
            #pragma unroll
            for (int r = 0; r < 8; r++)
                a[r] = fmaf(s_sh[r * 2048 + j * 8 + h], htv, a[r]);
        }
    }
    #pragma unroll
    for (int r = 0; r < 8; r++) redn[js * 512 + r * 64 + d] = a[r];
    __syncthreads();
    {
        int r = t >> 6, dd = t & 63;
        float s = 0.f;
        #pragma unroll
        for (int q = 0; q < 8; q++) s += redn[q * 512 + r * 64 + dd];
        g_nn[(size_t)(bi0 + r) * Dc + dd] = s;
    }
}

// ============================================================
// K3c: np = nn@Wn + bn; node LN; z1/z2 projections. 8 nodes/block.
// ============================================================
__global__ void __launch_bounds__(512, 1)
k3c_node(const float* __restrict__ Wn,
         const float* __restrict__ bn,
         const float* __restrict__ Wedge,
         const float* __restrict__ gamma_x,
         const float* __restrict__ beta_x,
         float* __restrict__ out_node) {
    __shared__ float nn_sh[8][Dc];
    __shared__ float np_sh[8][INc];
    __shared__ float vsh[8][INc];
    __shared__ float mean_sh[8], rstd_sh[8];
    int t = threadIdx.x, w = t >> 5, lane = t & 31;
    int bi0 = blockIdx.x * 8;

    if (t < 512) {
        int r = t >> 6, d = t & 63;
        nn_sh[r][d] = g_nn[(size_t)(bi0 + r) * Dc + d];
    }
    __syncthreads();

    int c = t & 255, rp = t >> 8;
    float np[4];
    #pragma unroll
    for (int rr = 0; rr < 4; rr++) np[rr] = bn[c];
    #pragma unroll 4
    for (int d = 0; d < Dc; d++) {
        float wv = Wn[(size_t)d * INc + c];
        #pragma unroll
        for (int rr = 0; rr < 4; rr++)
            np[rr] = fmaf(nn_sh[rp * 4 + rr][d], wv, np[rr]);
    }
    #pragma unroll
    for (int rr = 0; rr < 4; rr++) {
        int r = rp * 4 + rr;
        np_sh[r][c] = np[rr];
        vsh[r][c] = g_xn[(size_t)(bi0 + r) * INc + c] + np[rr];
    }
    __syncthreads();
    if (w < 8) {
        float s = 0.f, sq = 0.f;
        #pragma unroll
        for (int u = 0; u < 8; u++) {
            float v = vsh[w][lane + u * 32];
            s += v; sq = fmaf(v, v, sq);
        }
        #pragma unroll
        for (int off = 16; off > 0; off >>= 1) {
            s  += __shfl_xor_sync(0xffffffffu, s, off);
            sq += __shfl_xor_sync(0xffffffffu, sq, off);
        }
        if (lane == 0) {
            float mean = s * (1.f / 256.f);
            mean_sh[w] = mean;
            rstd_sh[w] = rsqrtf(sq * (1.f / 256.f) - mean * mean + LN_EPS);
        }
    }
    __syncthreads();
    #pragma unroll
    for (int rr = 0; rr < 4; rr++) {
        int r = rp * 4 + rr;
        out_node[(size_t)(bi0 + r) * INc + c] =
            (vsh[r][c] - mean_sh[r]) * rstd_sh[r] * gamma_x[c] + beta_x[c];
    }
    float z1a[4] = {0.f, 0.f, 0.f, 0.f}, z2a[4] = {0.f, 0.f, 0.f, 0.f};
    #pragma unroll 2
    for (int k = 0; k < INc; k++) {
        float w1 = Wedge[(size_t)k * INc + c];
        float w2 = Wedge[(size_t)(k + 256) * INc + c];
        #pragma unroll
        for (int rr = 0; rr < 4; rr++) {
            float npv = np_sh[rp * 4 + rr][k];
            z1a[rr] = fmaf(npv, w1, z1a[rr]);
            z2a[rr] = fmaf(npv, w2, z2a[rr]);
        }
    }
    #pragma unroll
    for (int rr = 0; rr < 4; rr++) {
        int r = rp * 4 + rr;
        g_z1[(size_t)(bi0 + r) * INc + c] = z1a[rr];
        g_z2[(size_t)(bi0 + r) * INc + c] = z2a[rr];
    }
}

// ============================================================
// K4: fp16 z3 GEMM + residual + LayerNorm. 256 threads, 8 warps.
// Block tile 64x256. Warp tile 64x32 (wc = warp). ldmatrix loads.
// SMEM u32: A[64][132]=8448 | B 3x[256][20]=15360 | z1/be/ga/bt
//           4x256 | red 512 | redq 512 | mean 64 | rstd 64
// ============================================================
#define K4_SMEM_B ((8448 + 15360 + 1024 + 512 + 512 + 64 + 64) * 4)
__global__ void __launch_bounds__(256, 1)
k4_fused(const float* __restrict__ emb_edge,
         const float* __restrict__ mask,
         const float* __restrict__ bedge,
         const float* __restrict__ gamma_e,
         const float* __restrict__ beta_e,
         float* __restrict__ out_edge) {
    extern __shared__ uint32_t su[];
    uint32_t* sA   = su;
    uint32_t* sB   = su + 8448;
    float*    sZ1  = (float*)(su + 23808);
    float*    sBE  = (float*)(su + 24064);
    float*    sGA  = (float*)(su + 24320);
    float*    sBT  = (float*)(su + 24576);
    float*    sRed = (float*)(su + 24832);
    float*    sRedQ= (float*)(su + 25344);
    float*    sMean= (float*)(su + 25856);
    float*    sRstd= (float*)(su + 25920);

    int t = threadIdx.x, wc = t >> 5, lane = t & 31;
    int g = lane >> 2, tig = lane & 3;
    int lm = lane & 7, lq = lane >> 3;
    int bid = blockIdx.x;
    int jt = bid & 3, i = (bid >> 2) & 255, b = bid >> 10;
    int j0 = jt * 64, bi = b * Nc + i;
    float mi = mask[bi];

    uint32_t sAsh = (uint32_t)__cvta_generic_to_shared(sA);
    uint32_t sBsh = (uint32_t)__cvta_generic_to_shared(sB);

    #pragma unroll
    for (int c = 0; c < 2; c++) {
        #pragma unroll
        for (int q = 0; q < 4; q++) {
            int t8 = q * 256 + t;
            int n = t8 >> 2, kq = t8 & 3;
            cp16(sBsh + (c * 5120 + n * 20 + kq * 4) * 4,
                 g_W316b + (size_t)c * 8192 + (size_t)t8 * 8);
        }
        CP_COMMIT;
    }

    #pragma unroll
    for (int u = 0; u < 16; u++) {
        int lin = u * 256 + t;
        int r = lin >> 6, c4 = lin & 63;
        float4 v = *(const float4*)(emb_edge +
            (((size_t)bi * Nc) + j0 + r) * INc + c4 * 4);
        float mm = mi * mask[b * Nc + j0 + r];
        __half2 h01 = __floats2half2_rn(v.x * mm, v.y * mm);
        __half2 h23 = __floats2half2_rn(v.z * mm, v.w * mm);
        uint32_t* dst = sA + r * 132 + c4 * 2;
        dst[0] = *reinterpret_cast<uint32_t*>(&h01);
        dst[1] = *reinterpret_cast<uint32_t*>(&h23);
    }
    sZ1[t] = g_z1[(size_t)bi * INc + t];
    sBE[t] = bedge[t]; sGA[t] = gamma_e[t]; sBT[t] = beta_e[t];

    int aRow = lm + (lq & 1) * 8;
    int aCol = (lq >> 1) * 8;
    int bRow = wc * 32 + (lq >> 1) * 8 + lm;
    int bCol = (lq & 1) * 8;

    float acc[4][4][4];
    #pragma unroll
    for (int m = 0; m < 4; m++)
        #pragma unroll
        for (int n = 0; n < 4; n++)
            #pragma unroll
            for (int e = 0; e < 4; e++) acc[m][n][e] = 0.f;

    for (int c = 0; c < 8; c++) {
        if (c < 7) { CP_WAIT1; } else { CP_WAIT0; }
        __syncthreads();
        if (c + 2 < 8) {
            int cc = c + 2;
            #pragma unroll
            for (int q = 0; q < 4; q++) {
                int t8 = q * 256 + t;
                int n = t8 >> 2, kq = t8 & 3;
                cp16(sBsh + ((cc % 3) * 5120 + n * 20 + kq * 4) * 4,
                     g_W316b + (size_t)cc * 8192 + (size_t)t8 * 8);
            }
            CP_COMMIT;
        }
        uint32_t stOff = sBsh + (c % 3) * 20480;
        #pragma unroll
        for (int kk = 0; kk < 2; kk++) {
            int kh = c * 32 + kk * 16;
            uint32_t af[4][4];
            #pragma unroll
            for (int mf = 0; mf < 4; mf++)
                ldsm4(af[mf], sAsh + ((mf * 16 + aRow) * 264 + kh + aCol) * 2);
            #pragma unroll
            for (int p = 0; p < 2; p++) {
                uint32_t bf[4];
                ldsm4(bf, stOff + ((bRow + p * 16) * 40 + kk * 16 + bCol) * 2);
                #pragma unroll
                for (int mf = 0; mf < 4; mf++) {
                    mma16(acc[mf][2 * p],     af[mf], bf[0], bf[1]);
                    mma16(acc[mf][2 * p + 1], af[mf], bf[2], bf[3]);
                }
            }
        }
    }

    // ---- epilogue: residual + LayerNorm over 256 cols ----
    float vv[4][2][8];
    #pragma unroll
    for (int mf = 0; mf < 4; mf++) {
        #pragma unroll
        for (int rh = 0; rh < 2; rh++) {
            int r = mf * 16 + g + 8 * rh;
            int j = j0 + r;
            float mm = mi * mask[b * Nc + j];
            const float* xerow = emb_edge + ((size_t)bi * Nc + j) * INc;
            const float* z2row = g_z2 + (size_t)(b * Nc + j) * INc;
            float sum = 0.f, sq = 0.f;
            #pragma unroll
            for (int n = 0; n < 4; n++) {
                int c0 = wc * 32 + n * 8 + 2 * tig;
                float2 xe2 = *(const float2*)(xerow + c0);
                float2 z22 = *(const float2*)(z2row + c0);
                float2 z12 = *(const float2*)(sZ1 + c0);
                float2 be2 = *(const float2*)(sBE + c0);
                float v0 = acc[mf][n][2 * rh]     + xe2.x * mm + z12.x + z22.x + be2.x;
                float v1 = acc[mf][n][2 * rh + 1] + xe2.y * mm + z12.y + z22.y + be2.y;
                vv[mf][rh][2 * n] = v0; vv[mf][rh][2 * n + 1] = v1;
                sum += v0 + v1;
                sq = fmaf(v0, v0, sq); sq = fmaf(v1, v1, sq);
            }
            sum += __shfl_xor_sync(0xffffffffu, sum, 1);
            sum += __shfl_xor_sync(0xffffffffu, sum, 2);
            sq  += __shfl_xor_sync(0xffffffffu, sq, 1);
            sq  += __shfl_xor_sync(0xffffffffu, sq, 2);
            if (tig == 0) { sRed[r * 8 + wc] = sum; sRedQ[r * 8 + wc] = sq; }
        }
    }
    __syncthreads();
    if (t < 64) {
        float s = 0.f, ss = 0.f;
        #pragma unroll
        for (int k = 0; k < 8; k++) { s += sRed[t * 8 + k]; ss += sRedQ[t * 8 + k]; }
        float mean = s * (1.f / 256.f);
        float var = ss * (1.f / 256.f) - mean * mean;
        sMean[t] = mean; sRstd[t] = rsqrtf(var + LN_EPS);
    }
    __syncthreads();
    #pragma unroll
    for (int mf = 0; mf < 4; mf++) {
        #pragma unroll
        for (int rh = 0; rh < 2; rh++) {
            int r = mf * 16 + g + 8 * rh;
            int j = j0 + r;
            float mean = sMean[r], rs = sRstd[r];
            float* orow = out_edge + ((size_t)bi * Nc + j) * INc;
            #pragma unroll
            for (int n = 0; n < 4; n++) {
                int c0 = wc * 32 + n * 8 + 2 * tig;
                float2 ga2 = *(const float2*)(sGA + c0);
                float2 bt2 = *(const float2*)(sBT + c0);
                float2 o;
                o.x = (vv[mf][rh][2 * n]     - mean) * rs * ga2.x + bt2.x;
                o.y = (vv[mf][rh][2 * n + 1] - mean) * rs * ga2.y + bt2.y;
                *(float2*)(orow + c0) = o;
            }
        }
    }
}

// ============================================================
extern "C" void kernel_launch(void* const* d_in, const int* in_sizes, int n_in,
                              void* d_out, int out_size) {
    const float* emb_node = (const float*)d_in[0];
    const float* emb_edge = (const float*)d_in[1];
    const float* adj      = (const float*)d_in[2];
    const float* mask     = (const float*)d_in[3];
    const float* Ws       = (const float*)d_in[4];
    const float* Wt       = (const float*)d_in[5];
    const float* We       = (const float*)d_in[6];
    const float* attn     = (const float*)d_in[7];
    const float* Wn       = (const float*)d_in[8];
    const float* bn       = (const float*)d_in[9];
    const float* Wedge    = (const float*)d_in[10];
    const float* bedge    = (const float*)d_in[11];
    const float* gamma_x  = (const float*)d_in[12];
    const float* beta_x   = (const float*)d_in[13];
    const float* gamma_e  = (const float*)d_in[14];
    const float* beta_e   = (const float*)d_in[15];

    float* out_node = (float*)d_out;
    float* out_edge = out_node + Bc * Nc * INc;

    cudaFuncSetAttribute(k2_scores, cudaFuncAttributeMaxDynamicSharedMemorySize,
                         K2_SMEM_B);
    cudaFuncSetAttribute(k3b_newnode, cudaFuncAttributeMaxDynamicSharedMemorySize,
                         K3B_SMEM_B);
    cudaFuncSetAttribute(k4_fused, cudaFuncAttributeMaxDynamicSharedMemorySize,
                         K4_SMEM_B);

    k0_prep<<<392, 512>>>(We, Wedge);
    k1_nodes<<<dim3(32, 2), 512>>>(emb_node, mask, Ws, Wt);
    k2_scores<<<Bc * Nc * 4, 256, K2_SMEM_B>>>(emb_edge, adj, mask, attn);
    k3b_newnode<<<dim3(32, 2), 512, K3B_SMEM_B>>>();
    k3c_node<<<64, 512>>>(Wn, bn, Wedge, gamma_x, beta_x, out_node);
    k4_fused<<<Bc * Nc * 4, 256, K4_SMEM_B>>>(emb_edge, mask, bedge,
                                              gamma_e, beta_e, out_edge);
}

// round 6
// speedup vs baseline: 4.4886x; 1.0014x over previous
#include <cuda_runtime.h>
#include <cuda_fp16.h>
#include <math.h>
#include <stdint.h>

#define Bc   2
#define Nc   256
#define INc  256
#define Hc   8
#define Dc   64
#define HDc  512
#define ALPHA 0.2f
#define LN_EPS 1e-5f

// ---- scratch ----
__device__ float g_xn[Bc * Nc * INc];
__device__ float g_hs[Bc * Nc * HDc];
__device__ float g_ht[Bc * Nc * HDc];
__device__ float g_scores[(size_t)Bc * Nc * Nc * Hc];
__device__ float g_den[Bc * Nc * Hc];
__device__ float g_nn[Bc * Nc * Dc];
__device__ float g_z1[Bc * Nc * INc];
__device__ float g_z2[Bc * Nc * INc];
// fp16 weights, k-blocked (32-wide) n-major: [k>>5][n][k&31]
__device__ __half g_We16b[INc * HDc];
__device__ __half g_W316b[INc * INc];

__device__ __forceinline__ void mma16(float* c, const uint32_t* a,
                                      uint32_t b0, uint32_t b1) {
    asm volatile(
        "mma.sync.aligned.m16n8k16.row.col.f32.f16.f16.f32 "
        "{%0,%1,%2,%3},{%4,%5,%6,%7},{%8,%9},{%0,%1,%2,%3};\n"
        : "+f"(c[0]), "+f"(c[1]), "+f"(c[2]), "+f"(c[3])
        : "r"(a[0]), "r"(a[1]), "r"(a[2]), "r"(a[3]), "r"(b0), "r"(b1));
}
__device__ __forceinline__ void ldsm4(uint32_t* r, uint32_t addr) {
    asm volatile("ldmatrix.sync.aligned.m8n8.x4.shared.b16 {%0,%1,%2,%3}, [%4];\n"
        : "=r"(r[0]), "=r"(r[1]), "=r"(r[2]), "=r"(r[3]) : "r"(addr));
}
__device__ __forceinline__ void cp16(uint32_t dst, const void* src) {
    asm volatile("cp.async.cg.shared.global [%0], [%1], 16;\n" :: "r"(dst), "l"(src));
}
#define CP_COMMIT asm volatile("cp.async.commit_group;\n" ::)
#define CP_WAIT1  asm volatile("cp.async.wait_group 1;\n" ::)
#define CP_WAIT0  asm volatile("cp.async.wait_group 0;\n" ::)

// ============================================================
// K0: convert weights to fp16 blocked layout; zero g_den
// ============================================================
__global__ void k0_prep(const float* __restrict__ We,
                        const float* __restrict__ Wedge) {
    int i = blockIdx.x * 512 + threadIdx.x;
    if (i < INc * HDc) {
        int k = i >> 9, n = i & 511;
        g_We16b[(k >> 5) * (512 * 32) + n * 32 + (k & 31)] = __float2half(We[i]);
    }
    int j = i - INc * HDc;
    if (j >= 0 && j < INc * INc) {
        int k = j >> 8, n = j & 255;
        g_W316b[(k >> 5) * (256 * 32) + n * 32 + (k & 31)] =
            __float2half(Wedge[(size_t)(512 + k) * 256 + n]);
    }
    int m = i - (INc * HDc + INc * INc);
    if (m >= 0 && m < Bc * Nc * Hc) g_den[m] = 0.f;
}

// ============================================================
// K1: xn = emb_node*mask; h_{s,t} = xn @ W{s,t}. 16 rows/block.
// ============================================================
__global__ void k1_nodes(const float* __restrict__ emb_node,
                         const float* __restrict__ mask,
                         const float* __restrict__ Ws,
                         const float* __restrict__ Wt) {
    __shared__ float xs[16][INc];
    int t = threadIdx.x;
    int n0 = blockIdx.x * 16;
    const float* W  = blockIdx.y ? Wt : Ws;
    float* out      = blockIdx.y ? g_ht : g_hs;
    #pragma unroll
    for (int u = 0; u < 8; u++) {
        int lin = u * 512 + t;
        int r = lin >> 8, c = lin & 255;
        float v = emb_node[(size_t)(n0 + r) * INc + c] * mask[n0 + r];
        xs[r][c] = v;
        if (blockIdx.y == 0) g_xn[(size_t)(n0 + r) * INc + c] = v;
    }
    __syncthreads();
    float a[16];
    #pragma unroll
    for (int r = 0; r < 16; r++) a[r] = 0.f;
    #pragma unroll 4
    for (int k = 0; k < INc; k++) {
        float wv = W[(size_t)k * HDc + t];
        #pragma unroll
        for (int r = 0; r < 16; r++) a[r] = fmaf(xs[r][k], wv, a[r]);
    }
    #pragma unroll
    for (int r = 0; r < 16; r++)
        out[(size_t)(n0 + r) * HDc + t] = a[r];
}

// ============================================================
// K2: fp16 scores kernel. 256 threads, 8 warps.
// Block tile 64x512, K=256 (8 k32 chunks). Warp tile 64x64:
// warp w = col group wc, all 4 row groups (mf). ldmatrix loads.
// SMEM u32: A[64][132]=8448 | B 3x[512][20]=30720 | hs 512 | at 512
// ============================================================
#define K2_SMEM_B ((8448 + 30720 + 512 + 512) * 4)
__global__ void __launch_bounds__(256, 1)
k2_scores(const float* __restrict__ emb_edge,
          const float* __restrict__ adj,
          const float* __restrict__ mask,
          const float* __restrict__ attn) {
    extern __shared__ uint32_t su[];
    uint32_t* sA  = su;              // halves, row pitch 264 (132 u32)
    uint32_t* sB  = su + 8448;       // 3 stages, n-major pitch 40 halves
    float*    sHS = (float*)(su + 39168);
    float*    sAT = (float*)(su + 39680);

    int t = threadIdx.x, wc = t >> 5, lane = t & 31;
    int g = lane >> 2, tig = lane & 3;
    int lm = lane & 7, lq = lane >> 3;
    int bid = blockIdx.x;
    int jt = bid & 3, i = (bid >> 2) & 255, b = bid >> 10;
    int j0 = jt * 64, bi = b * Nc + i;
    float mi = mask[bi];

    uint32_t sAsh = (uint32_t)__cvta_generic_to_shared(sA);
    uint32_t sBsh = (uint32_t)__cvta_generic_to_shared(sB);

    // prefetch B chunks 0,1 (each 512n x 32k halves)
    #pragma unroll
    for (int c = 0; c < 2; c++) {
        #pragma unroll
        for (int q = 0; q < 8; q++) {
            int t8 = q * 256 + t;
            int n = t8 >> 2, kq = t8 & 3;
            cp16(sBsh + (c * 10240 + n * 20 + kq * 4) * 4,
                 g_We16b + (size_t)c * 16384 + (size_t)t8 * 8);
        }
        CP_COMMIT;
    }

    // stage A (masked xe -> fp16)
    #pragma unroll
    for (int u = 0; u < 16; u++) {
        int lin = u * 256 + t;
        int r = lin >> 6, c4 = lin & 63;
        float4 v = *(const float4*)(emb_edge +
            (((size_t)bi * Nc) + j0 + r) * INc + c4 * 4);
        float mm = mi * mask[b * Nc + j0 + r];
        __half2 h01 = __floats2half2_rn(v.x * mm, v.y * mm);
        __half2 h23 = __floats2half2_rn(v.z * mm, v.w * mm);
        uint32_t* dst = sA + r * 132 + c4 * 2;
        dst[0] = *reinterpret_cast<uint32_t*>(&h01);
        dst[1] = *reinterpret_cast<uint32_t*>(&h23);
    }
    #pragma unroll
    for (int u = 0; u < 2; u++) {
        sHS[u * 256 + t] = g_hs[(size_t)bi * HDc + u * 256 + t];
        sAT[u * 256 + t] = attn[u * 256 + t];
    }

    // ldmatrix per-lane address components
    int aRow = lm + (lq & 1) * 8;          // + mf*16
    int aCol = (lq >> 1) * 8;              // + kh (halves)
    int bRow = wc * 64 + (lq >> 1) * 8 + lm;  // + p*16
    int bCol = (lq & 1) * 8;               // + kk*16 (halves)

    float acc[4][8][4];
    #pragma unroll
    for (int m = 0; m < 4; m++)
        #pragma unroll
        for (int n = 0; n < 8; n++)
            #pragma unroll
            for (int e = 0; e < 4; e++) acc[m][n][e] = 0.f;

    for (int c = 0; c < 8; c++) {
        if (c < 7) { CP_WAIT1; } else { CP_WAIT0; }
        __syncthreads();
        if (c + 2 < 8) {
            int cc = c + 2;
            #pragma unroll
            for (int q = 0; q < 8; q++) {
                int t8 = q * 256 + t;
                int n = t8 >> 2, kq = t8 & 3;
                cp16(sBsh + ((cc % 3) * 10240 + n * 20 + kq * 4) * 4,
                     g_We16b + (size_t)cc * 16384 + (size_t)t8 * 8);
            }
            CP_COMMIT;
        }
        uint32_t stOff = sBsh + (c % 3) * 40960;
        #pragma unroll
        for (int kk = 0; kk < 2; kk++) {
            int kh = c * 32 + kk * 16;
            uint32_t af[4][4];
            #pragma unroll
            for (int mf = 0; mf < 4; mf++)
                ldsm4(af[mf], sAsh + ((mf * 16 + aRow) * 264 + kh + aCol) * 2);
            #pragma unroll
            for (int p = 0; p < 4; p++) {
                uint32_t bf[4];
                ldsm4(bf, stOff + ((bRow + p * 16) * 40 + kk * 16 + bCol) * 2);
                #pragma unroll
                for (int mf = 0; mf < 4; mf++) {
                    mma16(acc[mf][2 * p],     af[mf], bf[0], bf[1]);
                    mma16(acc[mf][2 * p + 1], af[mf], bf[2], bf[3]);
                }
            }
        }
    }

    // ---- epilogue: lrelu + attn-dot + exp + denom atomics ----
    float wsum = 0.f;
    #pragma unroll
    for (int mf = 0; mf < 4; mf++) {
        #pragma unroll
        for (int rh = 0; rh < 2; rh++) {
            int j = j0 + mf * 16 + g + 8 * rh;
            const float* htrow = g_ht + (size_t)(b * Nc + j) * HDc + wc * 64;
            float sum = 0.f;
            #pragma unroll
            for (int n = 0; n < 8; n++) {
                int c0 = n * 8 + 2 * tig;
                float2 hte = *(const float2*)(htrow + c0);
                float2 hs2 = *(const float2*)(sHS + wc * 64 + c0);
                float2 at2 = *(const float2*)(sAT + wc * 64 + c0);
                float v0 = acc[mf][n][2 * rh]     + hs2.x + hte.x;
                float v1 = acc[mf][n][2 * rh + 1] + hs2.y + hte.y;
                v0 = v0 > 0.f ? v0 : ALPHA * v0;
                v1 = v1 > 0.f ? v1 : ALPHA * v1;
                sum = fmaf(at2.x, v0, sum);
                sum = fmaf(at2.y, v1, sum);
            }
            sum += __shfl_xor_sync(0xffffffffu, sum, 1);
            sum += __shfl_xor_sync(0xffffffffu, sum, 2);
            if (tig == 0) {
                size_t e = (size_t)bi * Nc + j;
                float sv = expf(sum) * adj[e] * (mi * mask[b * Nc + j]);
                g_scores[e * 8 + wc] = sv;
                wsum += sv;
            }
        }
    }
    wsum += __shfl_xor_sync(0xffffffffu, wsum, 4);
    wsum += __shfl_xor_sync(0xffffffffu, wsum, 8);
    wsum += __shfl_xor_sync(0xffffffffu, wsum, 16);
    if (lane == 0) atomicAdd(&g_den[bi * 8 + wc], wsum);
}

// ============================================================
// K3b: new_node einsum. Block = (8 i rows, batch b). 512 thr.
// ============================================================
#define K3B_SMEM_B ((16384 + 64 + 4096) * 4)
__global__ void __launch_bounds__(512, 1) k3b_newnode() {
    extern __shared__ float smf[];
    float* s_sh = smf;            // [r][jh] pitch 2048
    float* inv  = smf + 16384;
    float* redn = smf + 16448;    // [js][r][d]

    int t = threadIdx.x;
    int b = blockIdx.y, i0 = blockIdx.x * 8, bi0 = b * Nc + i0;

    if (t < 64) {
        int r = t >> 3, h = t & 7;
        inv[t] = 1.f / (g_den[(bi0 + r) * 8 + h] + 1e-6f);
    }
    __syncthreads();
    #pragma unroll
    for (int u = 0; u < 32; u++) {
        int lin = u * 512 + t;
        int r = lin >> 11, jh = lin & 2047;
        s_sh[r * 2048 + jh] =
            g_scores[(size_t)(bi0 + r) * 2048 + jh] * inv[r * 8 + (jh & 7)];
    }
    __syncthreads();

    int js = t >> 6, d = t & 63;
    float a[8];
    #pragma unroll
    for (int r = 0; r < 8; r++) a[r] = 0.f;
    const float* htb = g_ht + (size_t)b * Nc * HDc;
    for (int j = js * 32; j < js * 32 + 32; j++) {
        const float* hp = htb + (size_t)j * HDc + d;
        #pragma unroll
        for (int h = 0; h < 8; h++) {
            float htv = hp[h * 64];
            #pragma unroll
            for (int r = 0; r < 8; r++)
                a[r] = fmaf(s_sh[r * 2048 + j * 8 + h], htv, a[r]);
        }
    }
    #pragma unroll
    for (int r = 0; r < 8; r++) redn[js * 512 + r * 64 + d] = a[r];
    __syncthreads();
    {
        int r = t >> 6, dd = t & 63;
        float s = 0.f;
        #pragma unroll
        for (int q = 0; q < 8; q++) s += redn[q * 512 + r * 64 + dd];
        g_nn[(size_t)(bi0 + r) * Dc + dd] = s;
    }
}

// ============================================================
// K3c: np = nn@Wn + bn; node LN; z1/z2 projections. 8 nodes/block.
// ============================================================
__global__ void __launch_bounds__(512, 1)
k3c_node(const float* __restrict__ Wn,
         const float* __restrict__ bn,
         const float* __restrict__ Wedge,
         const float* __restrict__ gamma_x,
         const float* __restrict__ beta_x,
         float* __restrict__ out_node) {
    __shared__ float nn_sh[8][Dc];
    __shared__ float np_sh[8][INc];
    __shared__ float vsh[8][INc];
    __shared__ float mean_sh[8], rstd_sh[8];
    int t = threadIdx.x, w = t >> 5, lane = t & 31;
    int bi0 = blockIdx.x * 8;

    if (t < 512) {
        int r = t >> 6, d = t & 63;
        nn_sh[r][d] = g_nn[(size_t)(bi0 + r) * Dc + d];
    }
    __syncthreads();

    int c = t & 255, rp = t >> 8;
    float np[4];
    #pragma unroll
    for (int rr = 0; rr < 4; rr++) np[rr] = bn[c];
    #pragma unroll 4
    for (int d = 0; d < Dc; d++) {
        float wv = Wn[(size_t)d * INc + c];
        #pragma unroll
        for (int rr = 0; rr < 4; rr++)
            np[rr] = fmaf(nn_sh[rp * 4 + rr][d], wv, np[rr]);
    }
    #pragma unroll
    for (int rr = 0; rr < 4; rr++) {
        int r = rp * 4 + rr;
        np_sh[r][c] = np[rr];
        vsh[r][c] = g_xn[(size_t)(bi0 + r) * INc + c] + np[rr];
    }
    __syncthreads();
    if (w < 8) {
        float s = 0.f, sq = 0.f;
        #pragma unroll
        for (int u = 0; u < 8; u++) {
            float v = vsh[w][lane + u * 32];
            s += v; sq = fmaf(v, v, sq);
        }
        #pragma unroll
        for (int off = 16; off > 0; off >>= 1) {
            s  += __shfl_xor_sync(0xffffffffu, s, off);
            sq += __shfl_xor_sync(0xffffffffu, sq, off);
        }
        if (lane == 0) {
            float mean = s * (1.f / 256.f);
            mean_sh[w] = mean;
            rstd_sh[w] = rsqrtf(sq * (1.f / 256.f) - mean * mean + LN_EPS);
        }
    }
    __syncthreads();
    #pragma unroll
    for (int rr = 0; rr < 4; rr++) {
        int r = rp * 4 + rr;
        out_node[(size_t)(bi0 + r) * INc + c] =
            (vsh[r][c] - mean_sh[r]) * rstd_sh[r] * gamma_x[c] + beta_x[c];
    }
    float z1a[4] = {0.f, 0.f, 0.f, 0.f}, z2a[4] = {0.f, 0.f, 0.f, 0.f};
    #pragma unroll 2
    for (int k = 0; k < INc; k++) {
        float w1 = Wedge[(size_t)k * INc + c];
        float w2 = Wedge[(size_t)(k + 256) * INc + c];
        #pragma unroll
        for (int rr = 0; rr < 4; rr++) {
            float npv = np_sh[rp * 4 + rr][k];
            z1a[rr] = fmaf(npv, w1, z1a[rr]);
            z2a[rr] = fmaf(npv, w2, z2a[rr]);
        }
    }
    #pragma unroll
    for (int rr = 0; rr < 4; rr++) {
        int r = rp * 4 + rr;
        g_z1[(size_t)(bi0 + r) * INc + c] = z1a[rr];
        g_z2[(size_t)(bi0 + r) * INc + c] = z2a[rr];
    }
}

// ============================================================
// K4: fp16 z3 GEMM + residual + LayerNorm. 256 threads, 8 warps.
// Block tile 64x256. Warp tile 64x32 (wc = warp). ldmatrix loads.
// SMEM u32: A[64][132]=8448 | B 3x[256][20]=15360 | z1/be/ga/bt
//           4x256 | red 512 | redq 512 | mean 64 | rstd 64
// ============================================================
#define K4_SMEM_B ((8448 + 15360 + 1024 + 512 + 512 + 64 + 64) * 4)
__global__ void __launch_bounds__(256, 1)
k4_fused(const float* __restrict__ emb_edge,
         const float* __restrict__ mask,
         const float* __restrict__ bedge,
         const float* __restrict__ gamma_e,
         const float* __restrict__ beta_e,
         float* __restrict__ out_edge) {
    extern __shared__ uint32_t su[];
    uint32_t* sA   = su;
    uint32_t* sB   = su + 8448;
    float*    sZ1  = (float*)(su + 23808);
    float*    sBE  = (float*)(su + 24064);
    float*    sGA  = (float*)(su + 24320);
    float*    sBT  = (float*)(su + 24576);
    float*    sRed = (float*)(su + 24832);
    float*    sRedQ= (float*)(su + 25344);
    float*    sMean= (float*)(su + 25856);
    float*    sRstd= (float*)(su + 25920);

    int t = threadIdx.x, wc = t >> 5, lane = t & 31;
    int g = lane >> 2, tig = lane & 3;
    int lm = lane & 7, lq = lane >> 3;
    int bid = blockIdx.x;
    int jt = bid & 3, i = (bid >> 2) & 255, b = bid >> 10;
    int j0 = jt * 64, bi = b * Nc + i;
    float mi = mask[bi];

    uint32_t sAsh = (uint32_t)__cvta_generic_to_shared(sA);
    uint32_t sBsh = (uint32_t)__cvta_generic_to_shared(sB);

    #pragma unroll
    for (int c = 0; c < 2; c++) {
        #pragma unroll
        for (int q = 0; q < 4; q++) {
            int t8 = q * 256 + t;
            int n = t8 >> 2, kq = t8 & 3;
            cp16(sBsh + (c * 5120 + n * 20 + kq * 4) * 4,
                 g_W316b + (size_t)c * 8192 + (size_t)t8 * 8);
        }
        CP_COMMIT;
    }

    #pragma unroll
    for (int u = 0; u < 16; u++) {
        int lin = u * 256 + t;
        int r = lin >> 6, c4 = lin & 63;
        float4 v = *(const float4*)(emb_edge +
            (((size_t)bi * Nc) + j0 + r) * INc + c4 * 4);
        float mm = mi * mask[b * Nc + j0 + r];
        __half2 h01 = __floats2half2_rn(v.x * mm, v.y * mm);
        __half2 h23 = __floats2half2_rn(v.z * mm, v.w * mm);
        uint32_t* dst = sA + r * 132 + c4 * 2;
        dst[0] = *reinterpret_cast<uint32_t*>(&h01);
        dst[1] = *reinterpret_cast<uint32_t*>(&h23);
    }
    sZ1[t] = g_z1[(size_t)bi * INc + t];
    sBE[t] = bedge[t]; sGA[t] = gamma_e[t]; sBT[t] = beta_e[t];

    int aRow = lm + (lq & 1) * 8;
    int aCol = (lq >> 1) * 8;
    int bRow = wc * 32 + (lq >> 1) * 8 + lm;
    int bCol = (lq & 1) * 8;

    float acc[4][4][4];
    #pragma unroll
    for (int m = 0; m < 4; m++)
        #pragma unroll
        for (int n = 0; n < 4; n++)
            #pragma unroll
            for (int e = 0; e < 4; e++) acc[m][n][e] = 0.f;

    for (int c = 0; c < 8; c++) {
        if (c < 7) { CP_WAIT1; } else { CP_WAIT0; }
        __syncthreads();
        if (c + 2 < 8) {
            int cc = c + 2;
            #pragma unroll
            for (int q = 0; q < 4; q++) {
                int t8 = q * 256 + t;
                int n = t8 >> 2, kq = t8 & 3;
                cp16(sBsh + ((cc % 3) * 5120 + n * 20 + kq * 4) * 4,
                     g_W316b + (size_t)cc * 8192 + (size_t)t8 * 8);
            }
            CP_COMMIT;
        }
        uint32_t stOff = sBsh + (c % 3) * 20480;
        #pragma unroll
        for (int kk = 0; kk < 2; kk++) {
            int kh = c * 32 + kk * 16;
            uint32_t af[4][4];
            #pragma unroll
            for (int mf = 0; mf < 4; mf++)
                ldsm4(af[mf], sAsh + ((mf * 16 + aRow) * 264 + kh + aCol) * 2);
            #pragma unroll
            for (int p = 0; p < 2; p++) {
                uint32_t bf[4];
                ldsm4(bf, stOff + ((bRow + p * 16) * 40 + kk * 16 + bCol) * 2);
                #pragma unroll
                for (int mf = 0; mf < 4; mf++) {
                    mma16(acc[mf][2 * p],     af[mf], bf[0], bf[1]);
                    mma16(acc[mf][2 * p + 1], af[mf], bf[2], bf[3]);
                }
            }
        }
    }

    // ---- epilogue: residual + LayerNorm over 256 cols ----
    float vv[4][2][8];
    #pragma unroll
    for (int mf = 0; mf < 4; mf++) {
        #pragma unroll
        for (int rh = 0; rh < 2; rh++) {
            int r = mf * 16 + g + 8 * rh;
            int j = j0 + r;
            float mm = mi * mask[b * Nc + j];
            const float* xerow = emb_edge + ((size_t)bi * Nc + j) * INc;
            const float* z2row = g_z2 + (size_t)(b * Nc + j) * INc;
            float sum = 0.f, sq = 0.f;
            #pragma unroll
            for (int n = 0; n < 4; n++) {
                int c0 = wc * 32 + n * 8 + 2 * tig;
                float2 xe2 = *(const float2*)(xerow + c0);
                float2 z22 = *(const float2*)(z2row + c0);
                float2 z12 = *(const float2*)(sZ1 + c0);
                float2 be2 = *(const float2*)(sBE + c0);
                float v0 = acc[mf][n][2 * rh]     + xe2.x * mm + z12.x + z22.x + be2.x;
                float v1 = acc[mf][n][2 * rh + 1] + xe2.y * mm + z12.y + z22.y + be2.y;
                vv[mf][rh][2 * n] = v0; vv[mf][rh][2 * n + 1] = v1;
                sum += v0 + v1;
                sq = fmaf(v0, v0, sq); sq = fmaf(v1, v1, sq);
            }
            sum += __shfl_xor_sync(0xffffffffu, sum, 1);
            sum += __shfl_xor_sync(0xffffffffu, sum, 2);
            sq  += __shfl_xor_sync(0xffffffffu, sq, 1);
            sq  += __shfl_xor_sync(0xffffffffu, sq, 2);
            if (tig == 0) { sRed[r * 8 + wc] = sum; sRedQ[r * 8 + wc] = sq; }
        }
    }
    __syncthreads();
    if (t < 64) {
        float s = 0.f, ss = 0.f;
        #pragma unroll
        for (int k = 0; k < 8; k++) { s += sRed[t * 8 + k]; ss += sRedQ[t * 8 + k]; }
        float mean = s * (1.f / 256.f);
        float var = ss * (1.f / 256.f) - mean * mean;
        sMean[t] = mean; sRstd[t] = rsqrtf(var + LN_EPS);
    }
    __syncthreads();
    #pragma unroll
    for (int mf = 0; mf < 4; mf++) {
        #pragma unroll
        for (int rh = 0; rh < 2; rh++) {
            int r = mf * 16 + g + 8 * rh;
            int j = j0 + r;
            float mean = sMean[r], rs = sRstd[r];
            float* orow = out_edge + ((size_t)bi * Nc + j) * INc;
            #pragma unroll
            for (int n = 0; n < 4; n++) {
                int c0 = wc * 32 + n * 8 + 2 * tig;
                float2 ga2 = *(const float2*)(sGA + c0);
                float2 bt2 = *(const float2*)(sBT + c0);
                float2 o;
                o.x = (vv[mf][rh][2 * n]     - mean) * rs * ga2.x + bt2.x;
                o.y = (vv[mf][rh][2 * n + 1] - mean) * rs * ga2.y + bt2.y;
                *(float2*)(orow + c0) = o;
            }
        }
    }
}

// ============================================================
extern "C" void kernel_launch(void* const* d_in, const int* in_sizes, int n_in,
                              void* d_out, int out_size) {
    const float* emb_node = (const float*)d_in[0];
    const float* emb_edge = (const float*)d_in[1];
    const float* adj      = (const float*)d_in[2];
    const float* mask     = (const float*)d_in[3];
    const float* Ws       = (const float*)d_in[4];
    const float* Wt       = (const float*)d_in[5];
    const float* We       = (const float*)d_in[6];
    const float* attn     = (const float*)d_in[7];
    const float* Wn       = (const float*)d_in[8];
    const float* bn       = (const float*)d_in[9];
    const float* Wedge    = (const float*)d_in[10];
    const float* bedge    = (const float*)d_in[11];
    const float* gamma_x  = (const float*)d_in[12];
    const float* beta_x   = (const float*)d_in[13];
    const float* gamma_e  = (const float*)d_in[14];
    const float* beta_e   = (const float*)d_in[15];

    float* out_node = (float*)d_out;
    float* out_edge = out_node + Bc * Nc * INc;

    cudaFuncSetAttribute(k2_scores, cudaFuncAttributeMaxDynamicSharedMemorySize,
                         K2_SMEM_B);
    cudaFuncSetAttribute(k3b_newnode, cudaFuncAttributeMaxDynamicSharedMemorySize,
                         K3B_SMEM_B);
    cudaFuncSetAttribute(k4_fused, cudaFuncAttributeMaxDynamicSharedMemorySize,
                         K4_SMEM_B);

    k0_prep<<<392, 512>>>(We, Wedge);
    k1_nodes<<<dim3(32, 2), 512>>>(emb_node, mask, Ws, Wt);
    k2_scores<<<Bc * Nc * 4, 256, K2_SMEM_B>>>(emb_edge, adj, mask, attn);
    k3b_newnode<<<dim3(32, 2), 512, K3B_SMEM_B>>>();
    k3c_node<<<64, 512>>>(Wn, bn, Wedge, gamma_x, beta_x, out_node);
    k4_fused<<<Bc * Nc * 4, 256, K4_SMEM_B>>>(emb_edge, mask, bedge,
                                              gamma_e, beta_e, out_edge);
}